// round 2
// baseline (speedup 1.0000x reference)
#include <cuda_runtime.h>
#include <math.h>

// ---------------- problem constants ----------------
#define TOKS   1024
#define EMB    256
#define NHEADS 8
#define HDIM   32
#define BBATCH 8
#define NLAYER 8
#define HIDDEN 512
#define SCALE_ATTN 0.17677669529663687f   // 32^-0.5

// ---------------- scratch (device globals; no allocation allowed) ----------------
__device__ float g_y   [BBATCH*TOKS*EMB];            // 8 MB  LN output
__device__ float g_qkv [BBATCH*TOKS*3*EMB];          // 24 MB
__device__ float g_o   [BBATCH*TOKS*EMB];            // 8 MB  attention output
__device__ float g_hid [BBATCH*HIDDEN*TOKS];         // 16 MB [B,HID,N]
__device__ float g_hid2[BBATCH*HIDDEN*TOKS];         // 16 MB

__device__ __forceinline__ float gelu_f(float x) {
    return 0.5f * x * (1.0f + erff(x * 0.70710678118654752f));
}

// ---------------- patch embed: conv stride 8 == per-patch 64->256 matvec ----------------
__global__ void __launch_bounds__(256) patch_embed_k(
    const float* __restrict__ x, const float* __restrict__ pw,
    const float* __restrict__ pb, const float* __restrict__ te,
    float* __restrict__ tok)
{
    int t = blockIdx.x;            // b*1024 + n
    int b = t >> 10, n = t & 1023;
    int pi = n >> 5, pj = n & 31;
    __shared__ float patch[64];
    int tid = threadIdx.x;
    if (tid < 64) {
        int r = tid >> 3, c = tid & 7;
        patch[tid] = x[((size_t)b*256 + (size_t)pi*8 + r)*256 + pj*8 + c];
    }
    __syncthreads();
    float acc = pb[tid] + te[tid];          // type_embed row 0
    const float* w = pw + tid*64;
    #pragma unroll
    for (int k = 0; k < 64; k++) acc = fmaf(w[k], patch[k], acc);
    tok[(size_t)t*EMB + tid] = acc;
}

// ---------------- layernorm: one warp per token, 8 ch per lane ----------------
__global__ void __launch_bounds__(256) layernorm_k(
    const float* __restrict__ in, const float* __restrict__ g,
    const float* __restrict__ bta, float* __restrict__ out)
{
    int warp = threadIdx.x >> 5, lane = threadIdx.x & 31;
    size_t t = (size_t)blockIdx.x*8 + warp;
    const float* row = in + t*EMB;
    float v[8]; float s = 0.f;
    #pragma unroll
    for (int i = 0; i < 8; i++) { v[i] = row[lane + i*32]; s += v[i]; }
    #pragma unroll
    for (int o = 16; o; o >>= 1) s += __shfl_xor_sync(0xffffffffu, s, o);
    float mean = s * (1.f/256.f);
    float var = 0.f;
    #pragma unroll
    for (int i = 0; i < 8; i++) { float d = v[i]-mean; var += d*d; }
    #pragma unroll
    for (int o = 16; o; o >>= 1) var += __shfl_xor_sync(0xffffffffu, var, o);
    float r = rsqrtf(var * (1.f/256.f) + 1e-5f);
    float* orow = out + t*EMB;
    #pragma unroll
    for (int i = 0; i < 8; i++) {
        int c = lane + i*32;
        orow[c] = (v[i]-mean)*r*g[c] + bta[c];
    }
}

// ---------------- generic tiled SGEMM: C[m,n] = sum_k A[m*sAm+k*sAk]*B[n*sBn+k*sBk] ----------------
__global__ void __launch_bounds__(256) gemm_k(
    const float* __restrict__ A, size_t sAb, int sAm, int sAk,
    const float* __restrict__ B, size_t sBb, int sBn, int sBk,
    float* __restrict__ C, size_t sCb,
    const float* __restrict__ bias, int biasPerM, int doGelu, int doResid,
    int N, int K)
{
    __shared__ float As[16][65];
    __shared__ float Bs[16][65];
    A += (size_t)blockIdx.z * sAb;
    B += (size_t)blockIdx.z * sBb;
    C += (size_t)blockIdx.z * sCb;
    int m0 = blockIdx.y*64, n0 = blockIdx.x*64;
    int tid = threadIdx.x;
    int tm = (tid >> 4) << 2, tn = (tid & 15) << 2;
    float acc[4][4] = {};
    for (int k0 = 0; k0 < K; k0 += 16) {
        if (sAk == 1) {
            int r = tid >> 2, c = (tid & 3) << 2;
            float4 v = *(const float4*)(A + (size_t)(m0+r)*sAm + k0 + c);
            As[c][r]=v.x; As[c+1][r]=v.y; As[c+2][r]=v.z; As[c+3][r]=v.w;
        } else {  // A is m-contiguous (pw2: A[m + k*1024])
            int r = tid & 63, cg = tid >> 6;
            #pragma unroll
            for (int i = 0; i < 4; i++) {
                int c = cg*4 + i;
                As[c][r] = A[(size_t)(m0+r)*sAm + (size_t)(k0+c)*sAk];
            }
        }
        {
            int r = tid >> 2, c = (tid & 3) << 2;
            float4 v = *(const float4*)(B + (size_t)(n0+r)*sBn + k0 + c);
            Bs[c][r]=v.x; Bs[c+1][r]=v.y; Bs[c+2][r]=v.z; Bs[c+3][r]=v.w;
        }
        __syncthreads();
        #pragma unroll
        for (int kk = 0; kk < 16; kk++) {
            float a[4], bb[4];
            #pragma unroll
            for (int i = 0; i < 4; i++) { a[i]=As[kk][tm+i]; bb[i]=Bs[kk][tn+i]; }
            #pragma unroll
            for (int i = 0; i < 4; i++)
                #pragma unroll
                for (int j = 0; j < 4; j++)
                    acc[i][j] = fmaf(a[i], bb[j], acc[i][j]);
        }
        __syncthreads();
    }
    #pragma unroll
    for (int i = 0; i < 4; i++) {
        int m = m0 + tm + i;
        float bm = (bias && biasPerM) ? bias[m] : 0.f;
        float* cp = C + (size_t)m*N + n0 + tn;
        float vals[4];
        #pragma unroll
        for (int j = 0; j < 4; j++) {
            float v = acc[i][j] + bm;
            if (bias && !biasPerM) v += bias[n0+tn+j];
            if (doGelu) v = gelu_f(v);
            vals[j] = v;
        }
        if (doResid) {
            float4 old = *(float4*)cp;
            vals[0]+=old.x; vals[1]+=old.y; vals[2]+=old.z; vals[3]+=old.w;
        }
        float4 res; res.x=vals[0]; res.y=vals[1]; res.z=vals[2]; res.w=vals[3];
        *(float4*)cp = res;
    }
}

// ---------------- fused flash attention: QK^T + rpb + gbias -> online softmax -> @V ----------------
// One block per (b*8+h, 64-query tile). 256 threads.
// S micro-tiling: thread t handles rows [t/16*4, +4), cols [(t%16)*4, +4) of the 64x64 S tile.
// O accumulation: same rows, head-dim cols [(t%16)*2, +2).
__global__ void __launch_bounds__(256) attn_k(
    const float* __restrict__ qkv, const float* __restrict__ rt,
    const float* __restrict__ gb, float* __restrict__ o)
{
    int bh = blockIdx.y; int b = bh >> 3, h = bh & 7;
    int n0 = blockIdx.x * 64;
    __shared__ float Qs[64][33];
    __shared__ float Ks[64][33];
    __shared__ float Vs[64][33];
    __shared__ float Ps[64][65];

    int tid = threadIdx.x;
    const float* qbase = qkv + (size_t)b*TOKS*768 + h*32;

    // load Q tile (64 rows x 32)
    int lr = tid >> 2, lc = (tid & 3) * 8;
    {
        const float* qp = qbase + (size_t)(n0 + lr)*768 + lc;
        #pragma unroll
        for (int i = 0; i < 8; i++) Qs[lr][lc + i] = qp[i];
    }

    int trow = (tid >> 4) << 2;      // S/O row base
    int tcol = (tid & 15) << 2;      // S col base
    int d0   = (tid & 15) << 1;      // O col base (head dim)

    float m_run[4], l_run[4];
    float Oacc[4][2] = {};
    #pragma unroll
    for (int i = 0; i < 4; i++) { m_run[i] = -1e30f; l_run[i] = 0.f; }

    // precompute rpb row components for this thread's rows
    int i1[4], j1[4];
    #pragma unroll
    for (int i = 0; i < 4; i++) { int n = n0 + trow + i; i1[i] = n >> 5; j1[i] = n & 31; }

    for (int k0 = 0; k0 < TOKS; k0 += 64) {
        // load K and V tiles
        {
            const float* kp = qbase + 256 + (size_t)(k0 + lr)*768 + lc;
            const float* vp = qbase + 512 + (size_t)(k0 + lr)*768 + lc;
            #pragma unroll
            for (int i = 0; i < 8; i++) { Ks[lr][lc + i] = kp[i]; Vs[lr][lc + i] = vp[i]; }
        }
        __syncthreads();

        // S = scale*Q.K^T + rpb + gbias
        float s[4][4] = {};
        #pragma unroll
        for (int d = 0; d < 32; d++) {
            float qa[4], ka[4];
            #pragma unroll
            for (int i = 0; i < 4; i++) { qa[i] = Qs[trow+i][d]; ka[i] = Ks[tcol+i][d]; }
            #pragma unroll
            for (int i = 0; i < 4; i++)
                #pragma unroll
                for (int j = 0; j < 4; j++)
                    s[i][j] = fmaf(qa[i], ka[j], s[i][j]);
        }
        #pragma unroll
        for (int i = 0; i < 4; i++) {
            int n = n0 + trow + i;
            const float* gbn = gb + (size_t)n*1024 + k0 + tcol;
            #pragma unroll
            for (int j = 0; j < 4; j++) {
                int m = k0 + tcol + j;
                int idx = (i1[i] - (m >> 5) + 31)*63 + (j1[i] - (m & 31) + 31);
                s[i][j] = s[i][j]*SCALE_ATTN + rt[idx*NHEADS + h] + gbn[j];
            }
        }

        // online softmax update
        float mnew[4], alpha[4], rsum[4];
        #pragma unroll
        for (int i = 0; i < 4; i++) {
            float rm = fmaxf(fmaxf(s[i][0], s[i][1]), fmaxf(s[i][2], s[i][3]));
            #pragma unroll
            for (int off = 8; off; off >>= 1)
                rm = fmaxf(rm, __shfl_xor_sync(0xffffffffu, rm, off));
            mnew[i] = fmaxf(m_run[i], rm);
            alpha[i] = __expf(m_run[i] - mnew[i]);
            float rs = 0.f;
            #pragma unroll
            for (int j = 0; j < 4; j++) { s[i][j] = __expf(s[i][j] - mnew[i]); rs += s[i][j]; }
            #pragma unroll
            for (int off = 8; off; off >>= 1)
                rs += __shfl_xor_sync(0xffffffffu, rs, off);
            l_run[i] = l_run[i]*alpha[i] + rs;
            m_run[i] = mnew[i];
        }

        // stage P, rescale O
        #pragma unroll
        for (int i = 0; i < 4; i++) {
            #pragma unroll
            for (int j = 0; j < 4; j++) Ps[trow+i][tcol+j] = s[i][j];
            Oacc[i][0] *= alpha[i];
            Oacc[i][1] *= alpha[i];
        }
        __syncthreads();

        // O += P @ V
        #pragma unroll 4
        for (int mm = 0; mm < 64; mm++) {
            float v0 = Vs[mm][d0], v1 = Vs[mm][d0+1];
            #pragma unroll
            for (int i = 0; i < 4; i++) {
                float p = Ps[trow+i][mm];
                Oacc[i][0] = fmaf(p, v0, Oacc[i][0]);
                Oacc[i][1] = fmaf(p, v1, Oacc[i][1]);
            }
        }
        __syncthreads();
    }

    #pragma unroll
    for (int i = 0; i < 4; i++) {
        float inv = 1.f / l_run[i];
        float* op = o + (size_t)(b*TOKS + n0 + trow + i)*EMB + h*32 + d0;
        op[0] = Oacc[i][0]*inv;
        op[1] = Oacc[i][1]*inv;
    }
}

// ---------------- depthwise 3x3 dilation-2 conv on 32x32 grid + bias + gelu ----------------
__global__ void __launch_bounds__(256) dwconv_k(
    const float* __restrict__ hid, const float* __restrict__ wd,
    const float* __restrict__ bd, float* __restrict__ out)
{
    int bc = blockIdx.x;                   // b*512 + c
    int c = bc & 511;
    __shared__ float t[32][32];
    const float* in = hid + (size_t)bc*1024;
    int tid = threadIdx.x;
    #pragma unroll
    for (int i = 0; i < 4; i++) { int p = tid + i*256; t[p>>5][p&31] = in[p]; }
    __syncthreads();
    float w[9];
    #pragma unroll
    for (int i = 0; i < 9; i++) w[i] = wd[c*9 + i];
    float bias = bd[c];
    #pragma unroll
    for (int i = 0; i < 4; i++) {
        int p = tid + i*256; int r = p >> 5, col = p & 31;
        float s = bias;
        #pragma unroll
        for (int u = 0; u < 3; u++)
            #pragma unroll
            for (int v = 0; v < 3; v++) {
                int rr = r + (u-1)*2, cc = col + (v-1)*2;
                if (rr >= 0 && rr < 32 && cc >= 0 && cc < 32)
                    s = fmaf(t[rr][cc], w[u*3+v], s);
            }
        out[(size_t)bc*1024 + p] = gelu_f(s);
    }
}

// ---------------- orchestration ----------------
extern "C" void kernel_launch(void* const* d_in, const int* in_sizes, int n_in,
                              void* d_out, int out_size)
{
    const float* x     = (const float*)d_in[0];
    const float* pw    = (const float*)d_in[1];
    const float* pb    = (const float*)d_in[2];
    const float* te    = (const float*)d_in[3];
    const float* qkvw  = (const float*)d_in[4];
    const float* projw = (const float*)d_in[5];
    const float* projb = (const float*)d_in[6];
    const float* ln1g  = (const float*)d_in[7];
    const float* ln1b  = (const float*)d_in[8];
    const float* ln2g  = (const float*)d_in[9];
    const float* ln2b  = (const float*)d_in[10];
    const float* rpbt  = (const float*)d_in[11];
    const float* gb    = (const float*)d_in[12];
    const float* pw1w  = (const float*)d_in[13];
    const float* pw1b  = (const float*)d_in[14];
    const float* dww   = (const float*)d_in[15];
    const float* dwb   = (const float*)d_in[16];
    const float* pw2w  = (const float*)d_in[17];
    const float* pw2b  = (const float*)d_in[18];
    float* tok = (float*)d_out;

    float *yb, *qkvb, *ob, *hid, *hid2;
    cudaGetSymbolAddress((void**)&yb,    g_y);
    cudaGetSymbolAddress((void**)&qkvb,  g_qkv);
    cudaGetSymbolAddress((void**)&ob,    g_o);
    cudaGetSymbolAddress((void**)&hid,   g_hid);
    cudaGetSymbolAddress((void**)&hid2,  g_hid2);

    patch_embed_k<<<BBATCH*TOKS, 256>>>(x, pw, pb, te, tok);

    for (int l = 0; l < NLAYER; l++) {
        // --- attention ---
        layernorm_k<<<1024, 256>>>(tok, ln1g + l*EMB, ln1b + l*EMB, yb);
        // qkv = y @ qkv_w^T : M=8192, N=768, K=256
        gemm_k<<<dim3(12, 128, 1), 256>>>(
            yb, 0, EMB, 1,
            qkvw + (size_t)l*768*EMB, 0, EMB, 1,
            qkvb, 0, nullptr, 0, 0, 0, 768, EMB);
        attn_k<<<dim3(16, 64), 256>>>(
            qkvb, rpbt + (size_t)l*3969*NHEADS, gb + (size_t)l*1024*1024, ob);
        // tok += o @ proj_w^T + proj_b : M=8192, N=256, K=256
        gemm_k<<<dim3(4, 128, 1), 256>>>(
            ob, 0, EMB, 1,
            projw + (size_t)l*EMB*EMB, 0, EMB, 1,
            tok, 0, projb + l*EMB, 0, 0, 1, EMB, EMB);

        // --- conv dilated MLP ---
        layernorm_k<<<1024, 256>>>(tok, ln2g + l*EMB, ln2b + l*EMB, yb);
        // hid[b,c,n] = gelu(pw1_w @ y^T + pw1_b[c]) : per-batch M=512, N=1024, K=256
        gemm_k<<<dim3(16, 8, BBATCH), 256>>>(
            pw1w + (size_t)l*HIDDEN*EMB, 0, EMB, 1,
            yb, (size_t)TOKS*EMB, EMB, 1,
            hid, (size_t)HIDDEN*TOKS, pw1b + l*HIDDEN, 1, 1, 0, TOKS, EMB);
        dwconv_k<<<BBATCH*HIDDEN, 256>>>(hid, dww + (size_t)l*HIDDEN*9, dwb + l*HIDDEN, hid2);
        // tok += hid2^T @ pw2_w^T + pw2_b : per-batch M=1024, N=256, K=512
        gemm_k<<<dim3(4, 16, BBATCH), 256>>>(
            hid2, (size_t)HIDDEN*TOKS, 1, TOKS,
            pw2w + (size_t)l*EMB*HIDDEN, 0, HIDDEN, 1,
            tok, (size_t)TOKS*EMB, pw2b + l*EMB, 0, 0, 1, EMB, HIDDEN);
    }
}

// round 3
// speedup vs baseline: 1.4287x; 1.4287x over previous
#include <cuda_runtime.h>
#include <math.h>

// ---------------- problem constants ----------------
#define TOKS   1024
#define EMB    256
#define NHEADS 8
#define HDIM   32
#define BBATCH 8
#define NLAYER 8
#define HIDDEN 512
#define SCALE_ATTN 0.17677669529663687f   // 32^-0.5

// ---------------- scratch (device globals; no allocation allowed) ----------------
__device__ float g_y   [BBATCH*TOKS*EMB];            // 8 MB  LN output
__device__ float g_qkv [BBATCH*TOKS*3*EMB];          // 24 MB
__device__ float g_o   [BBATCH*TOKS*EMB];            // 8 MB  attention output
__device__ float g_hid [BBATCH*HIDDEN*TOKS];         // 16 MB [B,HID,N]
__device__ float g_hid2[BBATCH*HIDDEN*TOKS];         // 16 MB

__device__ __forceinline__ float gelu_f(float x) {
    return 0.5f * x * (1.0f + erff(x * 0.70710678118654752f));
}

__device__ __forceinline__ unsigned f2tf32(float x) {
    unsigned u; asm("cvt.rna.tf32.f32 %0, %1;" : "=r"(u) : "f"(x)); return u;
}

__device__ __forceinline__ void mma_tf32(float* c,
    unsigned a0, unsigned a1, unsigned a2, unsigned a3,
    unsigned b0, unsigned b1)
{
    asm volatile(
        "mma.sync.aligned.m16n8k8.row.col.f32.tf32.tf32.f32 "
        "{%0,%1,%2,%3},{%4,%5,%6,%7},{%8,%9},{%0,%1,%2,%3};"
        : "+f"(c[0]), "+f"(c[1]), "+f"(c[2]), "+f"(c[3])
        : "r"(a0), "r"(a1), "r"(a2), "r"(a3), "r"(b0), "r"(b1));
}

// ---------------- patch embed: conv stride 8 == per-patch 64->256 matvec ----------------
__global__ void __launch_bounds__(256) patch_embed_k(
    const float* __restrict__ x, const float* __restrict__ pw,
    const float* __restrict__ pb, const float* __restrict__ te,
    float* __restrict__ tok)
{
    int t = blockIdx.x;            // b*1024 + n
    int b = t >> 10, n = t & 1023;
    int pi = n >> 5, pj = n & 31;
    __shared__ float patch[64];
    int tid = threadIdx.x;
    if (tid < 64) {
        int r = tid >> 3, c = tid & 7;
        patch[tid] = x[((size_t)b*256 + (size_t)pi*8 + r)*256 + pj*8 + c];
    }
    __syncthreads();
    float acc = pb[tid] + te[tid];          // type_embed row 0
    const float* w = pw + tid*64;
    #pragma unroll
    for (int k = 0; k < 64; k++) acc = fmaf(w[k], patch[k], acc);
    tok[(size_t)t*EMB + tid] = acc;
}

// ---------------- layernorm: one warp per token, 8 ch per lane ----------------
__global__ void __launch_bounds__(256) layernorm_k(
    const float* __restrict__ in, const float* __restrict__ g,
    const float* __restrict__ bta, float* __restrict__ out)
{
    int warp = threadIdx.x >> 5, lane = threadIdx.x & 31;
    size_t t = (size_t)blockIdx.x*8 + warp;
    const float* row = in + t*EMB;
    float v[8]; float s = 0.f;
    #pragma unroll
    for (int i = 0; i < 8; i++) { v[i] = row[lane + i*32]; s += v[i]; }
    #pragma unroll
    for (int o = 16; o; o >>= 1) s += __shfl_xor_sync(0xffffffffu, s, o);
    float mean = s * (1.f/256.f);
    float var = 0.f;
    #pragma unroll
    for (int i = 0; i < 8; i++) { float d = v[i]-mean; var += d*d; }
    #pragma unroll
    for (int o = 16; o; o >>= 1) var += __shfl_xor_sync(0xffffffffu, var, o);
    float r = rsqrtf(var * (1.f/256.f) + 1e-5f);
    float* orow = out + t*EMB;
    #pragma unroll
    for (int i = 0; i < 8; i++) {
        int c = lane + i*32;
        orow[c] = (v[i]-mean)*r*g[c] + bta[c];
    }
}

// ---------------- generic tiled SGEMM: C[m,n] = sum_k A[m*sAm+k*sAk]*B[n*sBn+k*sBk] ----------------
__global__ void __launch_bounds__(256) gemm_k(
    const float* __restrict__ A, size_t sAb, int sAm, int sAk,
    const float* __restrict__ B, size_t sBb, int sBn, int sBk,
    float* __restrict__ C, size_t sCb,
    const float* __restrict__ bias, int biasPerM, int doGelu, int doResid,
    int N, int K)
{
    __shared__ float As[16][65];
    __shared__ float Bs[16][65];
    A += (size_t)blockIdx.z * sAb;
    B += (size_t)blockIdx.z * sBb;
    C += (size_t)blockIdx.z * sCb;
    int m0 = blockIdx.y*64, n0 = blockIdx.x*64;
    int tid = threadIdx.x;
    int tm = (tid >> 4) << 2, tn = (tid & 15) << 2;
    float acc[4][4] = {};
    for (int k0 = 0; k0 < K; k0 += 16) {
        if (sAk == 1) {
            int r = tid >> 2, c = (tid & 3) << 2;
            float4 v = *(const float4*)(A + (size_t)(m0+r)*sAm + k0 + c);
            As[c][r]=v.x; As[c+1][r]=v.y; As[c+2][r]=v.z; As[c+3][r]=v.w;
        } else {  // A is m-contiguous (pw2: A[m + k*1024])
            int r = tid & 63, cg = tid >> 6;
            #pragma unroll
            for (int i = 0; i < 4; i++) {
                int c = cg*4 + i;
                As[c][r] = A[(size_t)(m0+r)*sAm + (size_t)(k0+c)*sAk];
            }
        }
        {
            int r = tid >> 2, c = (tid & 3) << 2;
            float4 v = *(const float4*)(B + (size_t)(n0+r)*sBn + k0 + c);
            Bs[c][r]=v.x; Bs[c+1][r]=v.y; Bs[c+2][r]=v.z; Bs[c+3][r]=v.w;
        }
        __syncthreads();
        #pragma unroll
        for (int kk = 0; kk < 16; kk++) {
            float a[4], bb[4];
            #pragma unroll
            for (int i = 0; i < 4; i++) { a[i]=As[kk][tm+i]; bb[i]=Bs[kk][tn+i]; }
            #pragma unroll
            for (int i = 0; i < 4; i++)
                #pragma unroll
                for (int j = 0; j < 4; j++)
                    acc[i][j] = fmaf(a[i], bb[j], acc[i][j]);
        }
        __syncthreads();
    }
    #pragma unroll
    for (int i = 0; i < 4; i++) {
        int m = m0 + tm + i;
        float bm = (bias && biasPerM) ? bias[m] : 0.f;
        float* cp = C + (size_t)m*N + n0 + tn;
        float vals[4];
        #pragma unroll
        for (int j = 0; j < 4; j++) {
            float v = acc[i][j] + bm;
            if (bias && !biasPerM) v += bias[n0+tn+j];
            if (doGelu) v = gelu_f(v);
            vals[j] = v;
        }
        if (doResid) {
            float4 old = *(float4*)cp;
            vals[0]+=old.x; vals[1]+=old.y; vals[2]+=old.z; vals[3]+=old.w;
        }
        float4 res; res.x=vals[0]; res.y=vals[1]; res.z=vals[2]; res.w=vals[3];
        *(float4*)cp = res;
    }
}

// ---------------- fused flash attention with tf32 tensor cores ----------------
// Block = 128 threads (4 warps), one (b*8+h, 64-query tile).
// Warp w owns query rows [n0 + w*16, +16). mma.m16n8k8.tf32 for QK^T and PV.
__global__ void __launch_bounds__(128) attn_k(
    const float* __restrict__ qkv, const float* __restrict__ rt,
    const float* __restrict__ gb, float* __restrict__ o)
{
    int bh = blockIdx.y; int b = bh >> 3, h = bh & 7;
    int n0 = blockIdx.x * 64;
    __shared__ float Qs[64][36];
    __shared__ float Ks[64][36];
    __shared__ float Vs[64][36];
    __shared__ float Ps[4][16][68];

    int tid = threadIdx.x;
    int warp = tid >> 5, lane = tid & 31;
    int gid = lane >> 2, tig = lane & 3;
    int wrow = warp * 16;

    const float* qbase = qkv + (size_t)b*TOKS*768 + h*32;

    // load Q (pre-scaled + tf32 rounded)
    {
        int r = tid >> 1, c0 = (tid & 1) * 16;
        const float* qp = qbase + (size_t)(n0 + r)*768 + c0;
        #pragma unroll
        for (int i = 0; i < 16; i += 4) {
            float4 v = *(const float4*)(qp + i);
            Qs[r][c0+i+0] = __uint_as_float(f2tf32(v.x * SCALE_ATTN));
            Qs[r][c0+i+1] = __uint_as_float(f2tf32(v.y * SCALE_ATTN));
            Qs[r][c0+i+2] = __uint_as_float(f2tf32(v.z * SCALE_ATTN));
            Qs[r][c0+i+3] = __uint_as_float(f2tf32(v.w * SCALE_ATTN));
        }
    }

    int n_lo = n0 + wrow + gid, n_hi = n_lo + 8;
    int i1l = n_lo >> 5, j1l = n_lo & 31;
    int i1h = n_hi >> 5, j1h = n_hi & 31;

    float m_run[2] = {-1e30f, -1e30f};
    float l_run[2] = {0.f, 0.f};
    float Oacc[4][4] = {};

    for (int k0 = 0; k0 < TOKS; k0 += 64) {
        __syncthreads();   // prev PV done before overwriting K/V (also covers Q on iter 0)
        {
            int r = tid >> 1, c0 = (tid & 1) * 16;
            const float* kp = qbase + 256 + (size_t)(k0 + r)*768 + c0;
            const float* vp = qbase + 512 + (size_t)(k0 + r)*768 + c0;
            #pragma unroll
            for (int i = 0; i < 16; i += 4) {
                float4 kv = *(const float4*)(kp + i);
                float4 vv = *(const float4*)(vp + i);
                Ks[r][c0+i+0] = __uint_as_float(f2tf32(kv.x));
                Ks[r][c0+i+1] = __uint_as_float(f2tf32(kv.y));
                Ks[r][c0+i+2] = __uint_as_float(f2tf32(kv.z));
                Ks[r][c0+i+3] = __uint_as_float(f2tf32(kv.w));
                Vs[r][c0+i+0] = __uint_as_float(f2tf32(vv.x));
                Vs[r][c0+i+1] = __uint_as_float(f2tf32(vv.y));
                Vs[r][c0+i+2] = __uint_as_float(f2tf32(vv.z));
                Vs[r][c0+i+3] = __uint_as_float(f2tf32(vv.w));
            }
        }
        __syncthreads();

        // ---- S = (scaled Q) K^T via mma ----
        float S[8][4] = {};
        #pragma unroll
        for (int kk = 0; kk < 32; kk += 8) {
            unsigned a0 = __float_as_uint(Qs[wrow+gid  ][kk+tig  ]);
            unsigned a1 = __float_as_uint(Qs[wrow+gid+8][kk+tig  ]);
            unsigned a2 = __float_as_uint(Qs[wrow+gid  ][kk+tig+4]);
            unsigned a3 = __float_as_uint(Qs[wrow+gid+8][kk+tig+4]);
            #pragma unroll
            for (int nf = 0; nf < 8; nf++) {
                unsigned b0 = __float_as_uint(Ks[nf*8+gid][kk+tig  ]);
                unsigned b1 = __float_as_uint(Ks[nf*8+gid][kk+tig+4]);
                mma_tf32(S[nf], a0, a1, a2, a3, b0, b1);
            }
        }

        // ---- add rpb + gbias, row max ----
        float mloc0 = -1e30f, mloc1 = -1e30f;
        #pragma unroll
        for (int nf = 0; nf < 8; nf++) {
            int m  = k0 + nf*8 + 2*tig;
            int i2a = m >> 5,       j2a = m & 31;
            int i2b = (m+1) >> 5,   j2b = (m+1) & 31;
            float2 gl = *(const float2*)(gb + (size_t)n_lo*1024 + m);
            float2 gh = *(const float2*)(gb + (size_t)n_hi*1024 + m);
            S[nf][0] += rt[((i1l-i2a+31)*63 + (j1l-j2a+31))*NHEADS + h] + gl.x;
            S[nf][1] += rt[((i1l-i2b+31)*63 + (j1l-j2b+31))*NHEADS + h] + gl.y;
            S[nf][2] += rt[((i1h-i2a+31)*63 + (j1h-j2a+31))*NHEADS + h] + gh.x;
            S[nf][3] += rt[((i1h-i2b+31)*63 + (j1h-j2b+31))*NHEADS + h] + gh.y;
            mloc0 = fmaxf(mloc0, fmaxf(S[nf][0], S[nf][1]));
            mloc1 = fmaxf(mloc1, fmaxf(S[nf][2], S[nf][3]));
        }
        #pragma unroll
        for (int off = 1; off < 4; off <<= 1) {
            mloc0 = fmaxf(mloc0, __shfl_xor_sync(0xffffffffu, mloc0, off));
            mloc1 = fmaxf(mloc1, __shfl_xor_sync(0xffffffffu, mloc1, off));
        }

        // ---- online softmax ----
        float mn0 = fmaxf(m_run[0], mloc0), mn1 = fmaxf(m_run[1], mloc1);
        float al0 = __expf(m_run[0] - mn0),  al1 = __expf(m_run[1] - mn1);
        float sl0 = 0.f, sl1 = 0.f;
        #pragma unroll
        for (int nf = 0; nf < 8; nf++) {
            S[nf][0] = __expf(S[nf][0] - mn0);
            S[nf][1] = __expf(S[nf][1] - mn0);
            S[nf][2] = __expf(S[nf][2] - mn1);
            S[nf][3] = __expf(S[nf][3] - mn1);
            sl0 += S[nf][0] + S[nf][1];
            sl1 += S[nf][2] + S[nf][3];
            Ps[warp][gid  ][nf*8 + 2*tig    ] = __uint_as_float(f2tf32(S[nf][0]));
            Ps[warp][gid  ][nf*8 + 2*tig + 1] = __uint_as_float(f2tf32(S[nf][1]));
            Ps[warp][gid+8][nf*8 + 2*tig    ] = __uint_as_float(f2tf32(S[nf][2]));
            Ps[warp][gid+8][nf*8 + 2*tig + 1] = __uint_as_float(f2tf32(S[nf][3]));
        }
        #pragma unroll
        for (int off = 1; off < 4; off <<= 1) {
            sl0 += __shfl_xor_sync(0xffffffffu, sl0, off);
            sl1 += __shfl_xor_sync(0xffffffffu, sl1, off);
        }
        l_run[0] = l_run[0]*al0 + sl0;
        l_run[1] = l_run[1]*al1 + sl1;
        m_run[0] = mn0; m_run[1] = mn1;
        #pragma unroll
        for (int df = 0; df < 4; df++) {
            Oacc[df][0] *= al0; Oacc[df][1] *= al0;
            Oacc[df][2] *= al1; Oacc[df][3] *= al1;
        }
        __syncwarp();

        // ---- O += P @ V via mma ----
        #pragma unroll
        for (int kk = 0; kk < 64; kk += 8) {
            unsigned a0 = __float_as_uint(Ps[warp][gid  ][kk+tig  ]);
            unsigned a1 = __float_as_uint(Ps[warp][gid+8][kk+tig  ]);
            unsigned a2 = __float_as_uint(Ps[warp][gid  ][kk+tig+4]);
            unsigned a3 = __float_as_uint(Ps[warp][gid+8][kk+tig+4]);
            #pragma unroll
            for (int df = 0; df < 4; df++) {
                unsigned b0 = __float_as_uint(Vs[kk+tig  ][df*8+gid]);
                unsigned b1 = __float_as_uint(Vs[kk+tig+4][df*8+gid]);
                mma_tf32(Oacc[df], a0, a1, a2, a3, b0, b1);
            }
        }
    }

    float inv0 = 1.f / l_run[0], inv1 = 1.f / l_run[1];
    float* olo = o + (size_t)(b*TOKS + n_lo)*EMB + h*32;
    float* ohi = o + (size_t)(b*TOKS + n_hi)*EMB + h*32;
    #pragma unroll
    for (int df = 0; df < 4; df++) {
        int d = df*8 + 2*tig;
        *(float2*)(olo + d) = make_float2(Oacc[df][0]*inv0, Oacc[df][1]*inv0);
        *(float2*)(ohi + d) = make_float2(Oacc[df][2]*inv1, Oacc[df][3]*inv1);
    }
}

// ---------------- depthwise 3x3 dilation-2 conv on 32x32 grid + bias + gelu ----------------
__global__ void __launch_bounds__(256) dwconv_k(
    const float* __restrict__ hid, const float* __restrict__ wd,
    const float* __restrict__ bd, float* __restrict__ out)
{
    int bc = blockIdx.x;                   // b*512 + c
    int c = bc & 511;
    __shared__ float t[32][32];
    const float* in = hid + (size_t)bc*1024;
    int tid = threadIdx.x;
    #pragma unroll
    for (int i = 0; i < 4; i++) { int p = tid + i*256; t[p>>5][p&31] = in[p]; }
    __syncthreads();
    float w[9];
    #pragma unroll
    for (int i = 0; i < 9; i++) w[i] = wd[c*9 + i];
    float bias = bd[c];
    #pragma unroll
    for (int i = 0; i < 4; i++) {
        int p = tid + i*256; int r = p >> 5, col = p & 31;
        float s = bias;
        #pragma unroll
        for (int u = 0; u < 3; u++)
            #pragma unroll
            for (int v = 0; v < 3; v++) {
                int rr = r + (u-1)*2, cc = col + (v-1)*2;
                if (rr >= 0 && rr < 32 && cc >= 0 && cc < 32)
                    s = fmaf(t[rr][cc], w[u*3+v], s);
            }
        out[(size_t)bc*1024 + p] = gelu_f(s);
    }
}

// ---------------- orchestration ----------------
extern "C" void kernel_launch(void* const* d_in, const int* in_sizes, int n_in,
                              void* d_out, int out_size)
{
    const float* x     = (const float*)d_in[0];
    const float* pw    = (const float*)d_in[1];
    const float* pb    = (const float*)d_in[2];
    const float* te    = (const float*)d_in[3];
    const float* qkvw  = (const float*)d_in[4];
    const float* projw = (const float*)d_in[5];
    const float* projb = (const float*)d_in[6];
    const float* ln1g  = (const float*)d_in[7];
    const float* ln1b  = (const float*)d_in[8];
    const float* ln2g  = (const float*)d_in[9];
    const float* ln2b  = (const float*)d_in[10];
    const float* rpbt  = (const float*)d_in[11];
    const float* gb    = (const float*)d_in[12];
    const float* pw1w  = (const float*)d_in[13];
    const float* pw1b  = (const float*)d_in[14];
    const float* dww   = (const float*)d_in[15];
    const float* dwb   = (const float*)d_in[16];
    const float* pw2w  = (const float*)d_in[17];
    const float* pw2b  = (const float*)d_in[18];
    float* tok = (float*)d_out;

    float *yb, *qkvb, *ob, *hid, *hid2;
    cudaGetSymbolAddress((void**)&yb,    g_y);
    cudaGetSymbolAddress((void**)&qkvb,  g_qkv);
    cudaGetSymbolAddress((void**)&ob,    g_o);
    cudaGetSymbolAddress((void**)&hid,   g_hid);
    cudaGetSymbolAddress((void**)&hid2,  g_hid2);

    patch_embed_k<<<BBATCH*TOKS, 256>>>(x, pw, pb, te, tok);

    for (int l = 0; l < NLAYER; l++) {
        // --- attention ---
        layernorm_k<<<1024, 256>>>(tok, ln1g + l*EMB, ln1b + l*EMB, yb);
        // qkv = y @ qkv_w^T : M=8192, N=768, K=256
        gemm_k<<<dim3(12, 128, 1), 256>>>(
            yb, 0, EMB, 1,
            qkvw + (size_t)l*768*EMB, 0, EMB, 1,
            qkvb, 0, nullptr, 0, 0, 0, 768, EMB);
        attn_k<<<dim3(16, 64), 128>>>(
            qkvb, rpbt + (size_t)l*3969*NHEADS, gb + (size_t)l*1024*1024, ob);
        // tok += o @ proj_w^T + proj_b : M=8192, N=256, K=256
        gemm_k<<<dim3(4, 128, 1), 256>>>(
            ob, 0, EMB, 1,
            projw + (size_t)l*EMB*EMB, 0, EMB, 1,
            tok, 0, projb + l*EMB, 0, 0, 1, EMB, EMB);

        // --- conv dilated MLP ---
        layernorm_k<<<1024, 256>>>(tok, ln2g + l*EMB, ln2b + l*EMB, yb);
        // hid[b,c,n] = gelu(pw1_w @ y^T + pw1_b[c]) : per-batch M=512, N=1024, K=256
        gemm_k<<<dim3(16, 8, BBATCH), 256>>>(
            pw1w + (size_t)l*HIDDEN*EMB, 0, EMB, 1,
            yb, (size_t)TOKS*EMB, EMB, 1,
            hid, (size_t)HIDDEN*TOKS, pw1b + l*HIDDEN, 1, 1, 0, TOKS, EMB);
        dwconv_k<<<BBATCH*HIDDEN, 256>>>(hid, dww + (size_t)l*HIDDEN*9, dwb + l*HIDDEN, hid2);
        // tok += hid2^T @ pw2_w^T + pw2_b : per-batch M=1024, N=256, K=512
        gemm_k<<<dim3(4, 16, BBATCH), 256>>>(
            hid2, (size_t)HIDDEN*TOKS, 1, TOKS,
            pw2w + (size_t)l*EMB*HIDDEN, 0, HIDDEN, 1,
            tok, (size_t)TOKS*EMB, pw2b + l*EMB, 0, 0, 1, EMB, HIDDEN);
    }
}

// round 4
// speedup vs baseline: 2.1890x; 1.5322x over previous
#include <cuda_runtime.h>
#include <math.h>

// ---------------- problem constants ----------------
#define TOKS   1024
#define EMB    256
#define NHEADS 8
#define HDIM   32
#define BBATCH 8
#define NLAYER 8
#define HIDDEN 512
#define SCALE_ATTN 0.17677669529663687f   // 32^-0.5

// ---------------- scratch (device globals; no allocation allowed) ----------------
__device__ float g_y   [BBATCH*TOKS*EMB];
__device__ float g_qkv [BBATCH*TOKS*3*EMB];
__device__ float g_o   [BBATCH*TOKS*EMB];
__device__ float g_hid [BBATCH*HIDDEN*TOKS];
__device__ float g_hid2[BBATCH*HIDDEN*TOKS];

__device__ __forceinline__ float gelu_f(float x) {
    return 0.5f * x * (1.0f + erff(x * 0.70710678118654752f));
}

__device__ __forceinline__ unsigned f2tf32(float x) {
    unsigned u; asm("cvt.rna.tf32.f32 %0, %1;" : "=r"(u) : "f"(x)); return u;
}

__device__ __forceinline__ void mma_tf32(float* c,
    unsigned a0, unsigned a1, unsigned a2, unsigned a3,
    unsigned b0, unsigned b1)
{
    asm volatile(
        "mma.sync.aligned.m16n8k8.row.col.f32.tf32.tf32.f32 "
        "{%0,%1,%2,%3},{%4,%5,%6,%7},{%8,%9},{%0,%1,%2,%3};"
        : "+f"(c[0]), "+f"(c[1]), "+f"(c[2]), "+f"(c[3])
        : "r"(a0), "r"(a1), "r"(a2), "r"(a3), "r"(b0), "r"(b1));
}

// ---------------- patch embed ----------------
__global__ void __launch_bounds__(256) patch_embed_k(
    const float* __restrict__ x, const float* __restrict__ pw,
    const float* __restrict__ pb, const float* __restrict__ te,
    float* __restrict__ tok)
{
    int t = blockIdx.x;
    int b = t >> 10, n = t & 1023;
    int pi = n >> 5, pj = n & 31;
    __shared__ float patch[64];
    int tid = threadIdx.x;
    if (tid < 64) {
        int r = tid >> 3, c = tid & 7;
        patch[tid] = x[((size_t)b*256 + (size_t)pi*8 + r)*256 + pj*8 + c];
    }
    __syncthreads();
    float acc = pb[tid] + te[tid];
    const float* w = pw + tid*64;
    #pragma unroll
    for (int k = 0; k < 64; k++) acc = fmaf(w[k], patch[k], acc);
    tok[(size_t)t*EMB + tid] = acc;
}

// ---------------- layernorm ----------------
__global__ void __launch_bounds__(256) layernorm_k(
    const float* __restrict__ in, const float* __restrict__ g,
    const float* __restrict__ bta, float* __restrict__ out)
{
    int warp = threadIdx.x >> 5, lane = threadIdx.x & 31;
    size_t t = (size_t)blockIdx.x*8 + warp;
    const float* row = in + t*EMB;
    float v[8]; float s = 0.f;
    #pragma unroll
    for (int i = 0; i < 8; i++) { v[i] = row[lane + i*32]; s += v[i]; }
    #pragma unroll
    for (int o = 16; o; o >>= 1) s += __shfl_xor_sync(0xffffffffu, s, o);
    float mean = s * (1.f/256.f);
    float var = 0.f;
    #pragma unroll
    for (int i = 0; i < 8; i++) { float d = v[i]-mean; var += d*d; }
    #pragma unroll
    for (int o = 16; o; o >>= 1) var += __shfl_xor_sync(0xffffffffu, var, o);
    float r = rsqrtf(var * (1.f/256.f) + 1e-5f);
    float* orow = out + t*EMB;
    #pragma unroll
    for (int i = 0; i < 8; i++) {
        int c = lane + i*32;
        orow[c] = (v[i]-mean)*r*g[c] + bta[c];
    }
}

// ---------------- tf32 tensor-core GEMM: C[M,N] (+)= A · B^T ----------------
// A: [M,K] row-major k-contig (transA=0) or A[m + k*lda] m-contig (transA=1)
// B: [N,K] row-major k-contig.  Tile 128x64x32, 256 threads, 8 warps (4x2).
__global__ void __launch_bounds__(256) gemm_tc(
    const float* __restrict__ A, size_t sAb, int transA, int lda,
    const float* __restrict__ B, size_t sBb,
    float* __restrict__ C, size_t sCb, int ldc,
    const float* __restrict__ bias, int biasPerM, int doGelu, int doResid,
    int K)
{
    __shared__ float As[128][36];
    __shared__ float Bs[64][36];
    A += (size_t)blockIdx.z * sAb;
    B += (size_t)blockIdx.z * sBb;
    C += (size_t)blockIdx.z * sCb;
    int m0 = blockIdx.y * 128, n0 = blockIdx.x * 64;
    int tid = threadIdx.x;
    int warp = tid >> 5, lane = tid & 31;
    int gid = lane >> 2, tig = lane & 3;
    int wm0 = (warp & 3) * 32, wn0 = (warp >> 2) * 32;

    float acc[2][4][4] = {};

    for (int k0 = 0; k0 < K; k0 += 32) {
        // ---- stage A ----
        if (!transA) {
            int r0 = tid >> 3, c = (tid & 7) * 4;
            #pragma unroll
            for (int i = 0; i < 4; i++) {
                int r = r0 + i*32;
                float4 v = *(const float4*)(A + (size_t)(m0+r)*lda + k0 + c);
                As[r][c+0] = __uint_as_float(f2tf32(v.x));
                As[r][c+1] = __uint_as_float(f2tf32(v.y));
                As[r][c+2] = __uint_as_float(f2tf32(v.z));
                As[r][c+3] = __uint_as_float(f2tf32(v.w));
            }
        } else {
            int k = tid >> 3, mb = tid & 7;
            const float* ak = A + (size_t)(k0 + k) * lda + m0;
            #pragma unroll
            for (int i = 0; i < 16; i++) {
                int m = mb + i*8;
                As[m][k] = __uint_as_float(f2tf32(ak[m]));
            }
        }
        // ---- stage B ----
        {
            int r = tid >> 2, c = (tid & 3) * 8;
            float4 v0 = *(const float4*)(B + (size_t)(n0+r)*K + k0 + c);
            float4 v1 = *(const float4*)(B + (size_t)(n0+r)*K + k0 + c + 4);
            Bs[r][c+0] = __uint_as_float(f2tf32(v0.x));
            Bs[r][c+1] = __uint_as_float(f2tf32(v0.y));
            Bs[r][c+2] = __uint_as_float(f2tf32(v0.z));
            Bs[r][c+3] = __uint_as_float(f2tf32(v0.w));
            Bs[r][c+4] = __uint_as_float(f2tf32(v1.x));
            Bs[r][c+5] = __uint_as_float(f2tf32(v1.y));
            Bs[r][c+6] = __uint_as_float(f2tf32(v1.z));
            Bs[r][c+7] = __uint_as_float(f2tf32(v1.w));
        }
        __syncthreads();

        #pragma unroll
        for (int kk = 0; kk < 32; kk += 8) {
            unsigned a[2][4], bfr[4][2];
            #pragma unroll
            for (int mi = 0; mi < 2; mi++) {
                int rb = wm0 + mi*16;
                a[mi][0] = __float_as_uint(As[rb+gid  ][kk+tig  ]);
                a[mi][1] = __float_as_uint(As[rb+gid+8][kk+tig  ]);
                a[mi][2] = __float_as_uint(As[rb+gid  ][kk+tig+4]);
                a[mi][3] = __float_as_uint(As[rb+gid+8][kk+tig+4]);
            }
            #pragma unroll
            for (int nf = 0; nf < 4; nf++) {
                bfr[nf][0] = __float_as_uint(Bs[wn0+nf*8+gid][kk+tig  ]);
                bfr[nf][1] = __float_as_uint(Bs[wn0+nf*8+gid][kk+tig+4]);
            }
            #pragma unroll
            for (int mi = 0; mi < 2; mi++)
                #pragma unroll
                for (int nf = 0; nf < 4; nf++)
                    mma_tf32(acc[mi][nf], a[mi][0], a[mi][1], a[mi][2], a[mi][3],
                             bfr[nf][0], bfr[nf][1]);
        }
        __syncthreads();
    }

    // ---- epilogue ----
    #pragma unroll
    for (int mi = 0; mi < 2; mi++) {
        int r0 = m0 + wm0 + mi*16 + gid;
        #pragma unroll
        for (int nf = 0; nf < 4; nf++) {
            int col = n0 + wn0 + nf*8 + 2*tig;
            float v0 = acc[mi][nf][0], v1 = acc[mi][nf][1];
            float v2 = acc[mi][nf][2], v3 = acc[mi][nf][3];
            if (bias) {
                if (biasPerM) {
                    float b0 = bias[r0], b1 = bias[r0+8];
                    v0 += b0; v1 += b0; v2 += b1; v3 += b1;
                } else {
                    float b0 = bias[col], b1 = bias[col+1];
                    v0 += b0; v1 += b1; v2 += b0; v3 += b1;
                }
            }
            if (doGelu) { v0 = gelu_f(v0); v1 = gelu_f(v1); v2 = gelu_f(v2); v3 = gelu_f(v3); }
            float* cl = C + (size_t)r0*ldc + col;
            float* ch = C + (size_t)(r0+8)*ldc + col;
            if (doResid) {
                float2 o0 = *(float2*)cl, o1 = *(float2*)ch;
                v0 += o0.x; v1 += o0.y; v2 += o1.x; v3 += o1.y;
            }
            *(float2*)cl = make_float2(v0, v1);
            *(float2*)ch = make_float2(v2, v3);
        }
    }
}

// ---------------- fused flash attention with tf32 tensor cores ----------------
__global__ void __launch_bounds__(128) attn_k(
    const float* __restrict__ qkv, const float* __restrict__ rt,
    const float* __restrict__ gb, float* __restrict__ o)
{
    int bh = blockIdx.y; int b = bh >> 3, h = bh & 7;
    int n0 = blockIdx.x * 64;
    __shared__ float Qs[64][36];
    __shared__ float Ks[64][36];
    __shared__ float Vs[64][36];
    __shared__ float Ps[4][16][68];

    int tid = threadIdx.x;
    int warp = tid >> 5, lane = tid & 31;
    int gid = lane >> 2, tig = lane & 3;
    int wrow = warp * 16;

    const float* qbase = qkv + (size_t)b*TOKS*768 + h*32;

    // load Q (pre-scaled + tf32 rounded)
    {
        int r = tid >> 1, c0 = (tid & 1) * 16;
        const float* qp = qbase + (size_t)(n0 + r)*768 + c0;
        #pragma unroll
        for (int i = 0; i < 16; i += 4) {
            float4 v = *(const float4*)(qp + i);
            Qs[r][c0+i+0] = __uint_as_float(f2tf32(v.x * SCALE_ATTN));
            Qs[r][c0+i+1] = __uint_as_float(f2tf32(v.y * SCALE_ATTN));
            Qs[r][c0+i+2] = __uint_as_float(f2tf32(v.z * SCALE_ATTN));
            Qs[r][c0+i+3] = __uint_as_float(f2tf32(v.w * SCALE_ATTN));
        }
    }
    __syncthreads();

    // hoist Q fragments into registers (loop-invariant)
    unsigned qa[4][4];
    #pragma unroll
    for (int kki = 0; kki < 4; kki++) {
        int kk = kki * 8;
        qa[kki][0] = __float_as_uint(Qs[wrow+gid  ][kk+tig  ]);
        qa[kki][1] = __float_as_uint(Qs[wrow+gid+8][kk+tig  ]);
        qa[kki][2] = __float_as_uint(Qs[wrow+gid  ][kk+tig+4]);
        qa[kki][3] = __float_as_uint(Qs[wrow+gid+8][kk+tig+4]);
    }

    int n_lo = n0 + wrow + gid, n_hi = n_lo + 8;
    int i1l = n_lo >> 5, j1l = n_lo & 31;
    int i1h = n_hi >> 5, j1h = n_hi & 31;

    float m_run[2] = {-1e30f, -1e30f};
    float l_run[2] = {0.f, 0.f};
    float Oacc[4][4] = {};

    for (int k0 = 0; k0 < TOKS; k0 += 64) {
        __syncthreads();
        {
            int r = tid >> 1, c0 = (tid & 1) * 16;
            const float* kp = qbase + 256 + (size_t)(k0 + r)*768 + c0;
            const float* vp = qbase + 512 + (size_t)(k0 + r)*768 + c0;
            #pragma unroll
            for (int i = 0; i < 16; i += 4) {
                float4 kv = *(const float4*)(kp + i);
                float4 vv = *(const float4*)(vp + i);
                Ks[r][c0+i+0] = __uint_as_float(f2tf32(kv.x));
                Ks[r][c0+i+1] = __uint_as_float(f2tf32(kv.y));
                Ks[r][c0+i+2] = __uint_as_float(f2tf32(kv.z));
                Ks[r][c0+i+3] = __uint_as_float(f2tf32(kv.w));
                Vs[r][c0+i+0] = __uint_as_float(f2tf32(vv.x));
                Vs[r][c0+i+1] = __uint_as_float(f2tf32(vv.y));
                Vs[r][c0+i+2] = __uint_as_float(f2tf32(vv.z));
                Vs[r][c0+i+3] = __uint_as_float(f2tf32(vv.w));
            }
        }
        __syncthreads();

        // ---- S = (scaled Q) K^T via mma ----
        float S[8][4] = {};
        #pragma unroll
        for (int kki = 0; kki < 4; kki++) {
            int kk = kki * 8;
            #pragma unroll
            for (int nf = 0; nf < 8; nf++) {
                unsigned b0 = __float_as_uint(Ks[nf*8+gid][kk+tig  ]);
                unsigned b1 = __float_as_uint(Ks[nf*8+gid][kk+tig+4]);
                mma_tf32(S[nf], qa[kki][0], qa[kki][1], qa[kki][2], qa[kki][3], b0, b1);
            }
        }

        // ---- add rpb + gbias, row max ----
        float mloc0 = -1e30f, mloc1 = -1e30f;
        #pragma unroll
        for (int nf = 0; nf < 8; nf++) {
            int m  = k0 + nf*8 + 2*tig;
            int i2a = m >> 5,       j2a = m & 31;
            int i2b = (m+1) >> 5,   j2b = (m+1) & 31;
            float2 gl = *(const float2*)(gb + (size_t)n_lo*1024 + m);
            float2 gh = *(const float2*)(gb + (size_t)n_hi*1024 + m);
            S[nf][0] += rt[((i1l-i2a+31)*63 + (j1l-j2a+31))*NHEADS + h] + gl.x;
            S[nf][1] += rt[((i1l-i2b+31)*63 + (j1l-j2b+31))*NHEADS + h] + gl.y;
            S[nf][2] += rt[((i1h-i2a+31)*63 + (j1h-j2a+31))*NHEADS + h] + gh.x;
            S[nf][3] += rt[((i1h-i2b+31)*63 + (j1h-j2b+31))*NHEADS + h] + gh.y;
            mloc0 = fmaxf(mloc0, fmaxf(S[nf][0], S[nf][1]));
            mloc1 = fmaxf(mloc1, fmaxf(S[nf][2], S[nf][3]));
        }
        #pragma unroll
        for (int off = 1; off < 4; off <<= 1) {
            mloc0 = fmaxf(mloc0, __shfl_xor_sync(0xffffffffu, mloc0, off));
            mloc1 = fmaxf(mloc1, __shfl_xor_sync(0xffffffffu, mloc1, off));
        }

        // ---- online softmax ----
        float mn0 = fmaxf(m_run[0], mloc0), mn1 = fmaxf(m_run[1], mloc1);
        float al0 = __expf(m_run[0] - mn0),  al1 = __expf(m_run[1] - mn1);
        float sl0 = 0.f, sl1 = 0.f;
        #pragma unroll
        for (int nf = 0; nf < 8; nf++) {
            S[nf][0] = __expf(S[nf][0] - mn0);
            S[nf][1] = __expf(S[nf][1] - mn0);
            S[nf][2] = __expf(S[nf][2] - mn1);
            S[nf][3] = __expf(S[nf][3] - mn1);
            sl0 += S[nf][0] + S[nf][1];
            sl1 += S[nf][2] + S[nf][3];
            Ps[warp][gid  ][nf*8 + 2*tig    ] = __uint_as_float(f2tf32(S[nf][0]));
            Ps[warp][gid  ][nf*8 + 2*tig + 1] = __uint_as_float(f2tf32(S[nf][1]));
            Ps[warp][gid+8][nf*8 + 2*tig    ] = __uint_as_float(f2tf32(S[nf][2]));
            Ps[warp][gid+8][nf*8 + 2*tig + 1] = __uint_as_float(f2tf32(S[nf][3]));
        }
        #pragma unroll
        for (int off = 1; off < 4; off <<= 1) {
            sl0 += __shfl_xor_sync(0xffffffffu, sl0, off);
            sl1 += __shfl_xor_sync(0xffffffffu, sl1, off);
        }
        l_run[0] = l_run[0]*al0 + sl0;
        l_run[1] = l_run[1]*al1 + sl1;
        m_run[0] = mn0; m_run[1] = mn1;
        #pragma unroll
        for (int df = 0; df < 4; df++) {
            Oacc[df][0] *= al0; Oacc[df][1] *= al0;
            Oacc[df][2] *= al1; Oacc[df][3] *= al1;
        }
        __syncwarp();

        // ---- O += P @ V via mma ----
        #pragma unroll
        for (int kk = 0; kk < 64; kk += 8) {
            unsigned a0 = __float_as_uint(Ps[warp][gid  ][kk+tig  ]);
            unsigned a1 = __float_as_uint(Ps[warp][gid+8][kk+tig  ]);
            unsigned a2 = __float_as_uint(Ps[warp][gid  ][kk+tig+4]);
            unsigned a3 = __float_as_uint(Ps[warp][gid+8][kk+tig+4]);
            #pragma unroll
            for (int df = 0; df < 4; df++) {
                unsigned b0 = __float_as_uint(Vs[kk+tig  ][df*8+gid]);
                unsigned b1 = __float_as_uint(Vs[kk+tig+4][df*8+gid]);
                mma_tf32(Oacc[df], a0, a1, a2, a3, b0, b1);
            }
        }
    }

    float inv0 = 1.f / l_run[0], inv1 = 1.f / l_run[1];
    float* olo = o + (size_t)(b*TOKS + n_lo)*EMB + h*32;
    float* ohi = o + (size_t)(b*TOKS + n_hi)*EMB + h*32;
    #pragma unroll
    for (int df = 0; df < 4; df++) {
        int d = df*8 + 2*tig;
        *(float2*)(olo + d) = make_float2(Oacc[df][0]*inv0, Oacc[df][1]*inv0);
        *(float2*)(ohi + d) = make_float2(Oacc[df][2]*inv1, Oacc[df][3]*inv1);
    }
}

// ---------------- depthwise 3x3 dilation-2 conv + bias + gelu ----------------
__global__ void __launch_bounds__(256) dwconv_k(
    const float* __restrict__ hid, const float* __restrict__ wd,
    const float* __restrict__ bd, float* __restrict__ out)
{
    int bc = blockIdx.x;
    int c = bc & 511;
    __shared__ float t[32][32];
    const float* in = hid + (size_t)bc*1024;
    int tid = threadIdx.x;
    #pragma unroll
    for (int i = 0; i < 4; i++) { int p = tid + i*256; t[p>>5][p&31] = in[p]; }
    __syncthreads();
    float w[9];
    #pragma unroll
    for (int i = 0; i < 9; i++) w[i] = wd[c*9 + i];
    float bias = bd[c];
    #pragma unroll
    for (int i = 0; i < 4; i++) {
        int p = tid + i*256; int r = p >> 5, col = p & 31;
        float s = bias;
        #pragma unroll
        for (int u = 0; u < 3; u++)
            #pragma unroll
            for (int v = 0; v < 3; v++) {
                int rr = r + (u-1)*2, cc = col + (v-1)*2;
                if (rr >= 0 && rr < 32 && cc >= 0 && cc < 32)
                    s = fmaf(t[rr][cc], w[u*3+v], s);
            }
        out[(size_t)bc*1024 + p] = gelu_f(s);
    }
}

// ---------------- orchestration ----------------
extern "C" void kernel_launch(void* const* d_in, const int* in_sizes, int n_in,
                              void* d_out, int out_size)
{
    const float* x     = (const float*)d_in[0];
    const float* pw    = (const float*)d_in[1];
    const float* pb    = (const float*)d_in[2];
    const float* te    = (const float*)d_in[3];
    const float* qkvw  = (const float*)d_in[4];
    const float* projw = (const float*)d_in[5];
    const float* projb = (const float*)d_in[6];
    const float* ln1g  = (const float*)d_in[7];
    const float* ln1b  = (const float*)d_in[8];
    const float* ln2g  = (const float*)d_in[9];
    const float* ln2b  = (const float*)d_in[10];
    const float* rpbt  = (const float*)d_in[11];
    const float* gb    = (const float*)d_in[12];
    const float* pw1w  = (const float*)d_in[13];
    const float* pw1b  = (const float*)d_in[14];
    const float* dww   = (const float*)d_in[15];
    const float* dwb   = (const float*)d_in[16];
    const float* pw2w  = (const float*)d_in[17];
    const float* pw2b  = (const float*)d_in[18];
    float* tok = (float*)d_out;

    float *yb, *qkvb, *ob, *hid, *hid2;
    cudaGetSymbolAddress((void**)&yb,    g_y);
    cudaGetSymbolAddress((void**)&qkvb,  g_qkv);
    cudaGetSymbolAddress((void**)&ob,    g_o);
    cudaGetSymbolAddress((void**)&hid,   g_hid);
    cudaGetSymbolAddress((void**)&hid2,  g_hid2);

    patch_embed_k<<<BBATCH*TOKS, 256>>>(x, pw, pb, te, tok);

    for (int l = 0; l < NLAYER; l++) {
        // --- attention ---
        layernorm_k<<<1024, 256>>>(tok, ln1g + l*EMB, ln1b + l*EMB, yb);
        // qkv = y @ qkv_w^T : M=8192, N=768, K=256
        gemm_tc<<<dim3(12, 64, 1), 256>>>(
            yb, 0, 0, EMB,
            qkvw + (size_t)l*768*EMB, 0,
            qkvb, 0, 768, nullptr, 0, 0, 0, EMB);
        attn_k<<<dim3(16, 64), 128>>>(
            qkvb, rpbt + (size_t)l*3969*NHEADS, gb + (size_t)l*1024*1024, ob);
        // tok += o @ proj_w^T + proj_b : M=8192, N=256, K=256
        gemm_tc<<<dim3(4, 64, 1), 256>>>(
            ob, 0, 0, EMB,
            projw + (size_t)l*EMB*EMB, 0,
            tok, 0, EMB, projb + l*EMB, 0, 0, 1, EMB);

        // --- conv dilated MLP ---
        layernorm_k<<<1024, 256>>>(tok, ln2g + l*EMB, ln2b + l*EMB, yb);
        // hid[b][c][n] = gelu(W1·Y^T + b1[c]) : per-batch M=512, N=1024, K=256
        gemm_tc<<<dim3(16, 4, BBATCH), 256>>>(
            pw1w + (size_t)l*HIDDEN*EMB, 0, 0, EMB,
            yb, (size_t)TOKS*EMB,
            hid, (size_t)HIDDEN*TOKS, TOKS, pw1b + l*HIDDEN, 1, 1, 0, EMB);
        dwconv_k<<<BBATCH*HIDDEN, 256>>>(hid, dww + (size_t)l*HIDDEN*9, dwb + l*HIDDEN, hid2);
        // tok += hid2^T · W2^T + b2 : per-batch M=1024, N=256, K=512 (A transposed)
        gemm_tc<<<dim3(4, 8, BBATCH), 256>>>(
            hid2, (size_t)HIDDEN*TOKS, 1, TOKS,
            pw2w + (size_t)l*EMB*HIDDEN, 0,
            tok, (size_t)TOKS*EMB, EMB, pw2b + l*EMB, 0, 0, 1, HIDDEN);
    }
}

// round 7
// speedup vs baseline: 2.2382x; 1.0225x over previous
#include <cuda_runtime.h>
#include <math.h>

// ---------------- problem constants ----------------
#define TOKS   1024
#define EMB    256
#define NHEADS 8
#define HDIM   32
#define BBATCH 8
#define NLAYER 8
#define HIDDEN 512
#define SCALE_ATTN 0.17677669529663687f   // 32^-0.5

// ---------------- scratch (device globals; no allocation allowed) ----------------
// Total 72 MB — identical footprint to the last passing rounds.
__device__ float g_y   [BBATCH*TOKS*EMB];            // 8 MB
__device__ float g_qkv [BBATCH*TOKS*3*EMB];          // 24 MB
__device__ float g_o   [BBATCH*TOKS*EMB];            // 8 MB
// g_big is phase-overlaid:
//   attention phase: biasf[h][n][m] = rpb + gbias   (all 8M floats)
//   MLP phase:       hid  = g_big[0 .. 4M), hid2 = g_big[4M .. 8M)
__device__ float g_big [NHEADS*TOKS*TOKS];           // 32 MB

__device__ __forceinline__ float gelu_f(float x) {
    return 0.5f * x * (1.0f + erff(x * 0.70710678118654752f));
}

__device__ __forceinline__ unsigned f2tf32(float x) {
    unsigned u; asm("cvt.rna.tf32.f32 %0, %1;" : "=r"(u) : "f"(x)); return u;
}

__device__ __forceinline__ void mma_tf32(float* c,
    unsigned a0, unsigned a1, unsigned a2, unsigned a3,
    unsigned b0, unsigned b1)
{
    asm volatile(
        "mma.sync.aligned.m16n8k8.row.col.f32.tf32.tf32.f32 "
        "{%0,%1,%2,%3},{%4,%5,%6,%7},{%8,%9},{%0,%1,%2,%3};"
        : "+f"(c[0]), "+f"(c[1]), "+f"(c[2]), "+f"(c[3])
        : "r"(a0), "r"(a1), "r"(a2), "r"(a3), "r"(b0), "r"(b1));
}

// ---------------- patch embed ----------------
__global__ void __launch_bounds__(256) patch_embed_k(
    const float* __restrict__ x, const float* __restrict__ pw,
    const float* __restrict__ pb, const float* __restrict__ te,
    float* __restrict__ tok)
{
    int t = blockIdx.x;
    int b = t >> 10, n = t & 1023;
    int pi = n >> 5, pj = n & 31;
    __shared__ float patch[64];
    int tid = threadIdx.x;
    if (tid < 64) {
        int r = tid >> 3, c = tid & 7;
        patch[tid] = x[((size_t)b*256 + (size_t)pi*8 + r)*256 + pj*8 + c];
    }
    __syncthreads();
    float acc = pb[tid] + te[tid];
    const float* w = pw + tid*64;
    #pragma unroll
    for (int k = 0; k < 64; k++) acc = fmaf(w[k], patch[k], acc);
    tok[(size_t)t*EMB + tid] = acc;
}

// ---------------- layernorm ----------------
__global__ void __launch_bounds__(256) layernorm_k(
    const float* __restrict__ in, const float* __restrict__ g,
    const float* __restrict__ bta, float* __restrict__ out)
{
    int warp = threadIdx.x >> 5, lane = threadIdx.x & 31;
    size_t t = (size_t)blockIdx.x*8 + warp;
    const float* row = in + t*EMB;
    float v[8]; float s = 0.f;
    #pragma unroll
    for (int i = 0; i < 8; i++) { v[i] = row[lane + i*32]; s += v[i]; }
    #pragma unroll
    for (int o = 16; o; o >>= 1) s += __shfl_xor_sync(0xffffffffu, s, o);
    float mean = s * (1.f/256.f);
    float var = 0.f;
    #pragma unroll
    for (int i = 0; i < 8; i++) { float d = v[i]-mean; var += d*d; }
    #pragma unroll
    for (int o = 16; o; o >>= 1) var += __shfl_xor_sync(0xffffffffu, var, o);
    float r = rsqrtf(var * (1.f/256.f) + 1e-5f);
    float* orow = out + t*EMB;
    #pragma unroll
    for (int i = 0; i < 8; i++) {
        int c = lane + i*32;
        orow[c] = (v[i]-mean)*r*g[c] + bta[c];
    }
}

// ---------------- combined attention bias: out[h][n][m] = rpb + gbias ----------------
__global__ void __launch_bounds__(256) biasprep_k(
    const float* __restrict__ rt, const float* __restrict__ gb,
    float* __restrict__ out)
{
    int n = blockIdx.x, h = blockIdx.y;
    int m0 = threadIdx.x * 4;
    int i1 = n >> 5, j1 = n & 31;
    float4 g = *(const float4*)(gb + (size_t)n*1024 + m0);
    float4 v;
    {
        int m = m0;
        v.x = rt[((i1-(m>>5)+31)*63 + (j1-(m&31)+31))*NHEADS + h] + g.x;
        m = m0+1;
        v.y = rt[((i1-(m>>5)+31)*63 + (j1-(m&31)+31))*NHEADS + h] + g.y;
        m = m0+2;
        v.z = rt[((i1-(m>>5)+31)*63 + (j1-(m&31)+31))*NHEADS + h] + g.z;
        m = m0+3;
        v.w = rt[((i1-(m>>5)+31)*63 + (j1-(m&31)+31))*NHEADS + h] + g.w;
    }
    *(float4*)(out + (((size_t)h<<20) | ((size_t)n<<10)) + m0) = v;
}

// ---------------- tf32 tensor-core GEMM: C[M,N] (+)= A · B^T ----------------
__global__ void __launch_bounds__(256) gemm_tc(
    const float* __restrict__ A, size_t sAb, int transA, int lda,
    const float* __restrict__ B, size_t sBb,
    float* __restrict__ C, size_t sCb, int ldc,
    const float* __restrict__ bias, int biasPerM, int doGelu, int doResid,
    int K)
{
    __shared__ float As[128][36];
    __shared__ float Bs[64][36];
    A += (size_t)blockIdx.z * sAb;
    B += (size_t)blockIdx.z * sBb;
    C += (size_t)blockIdx.z * sCb;
    int m0 = blockIdx.y * 128, n0 = blockIdx.x * 64;
    int tid = threadIdx.x;
    int warp = tid >> 5, lane = tid & 31;
    int gid = lane >> 2, tig = lane & 3;
    int wm0 = (warp & 3) * 32, wn0 = (warp >> 2) * 32;

    float acc[2][4][4] = {};

    for (int k0 = 0; k0 < K; k0 += 32) {
        if (!transA) {
            int r0 = tid >> 3, c = (tid & 7) * 4;
            #pragma unroll
            for (int i = 0; i < 4; i++) {
                int r = r0 + i*32;
                float4 v = *(const float4*)(A + (size_t)(m0+r)*lda + k0 + c);
                As[r][c+0] = __uint_as_float(f2tf32(v.x));
                As[r][c+1] = __uint_as_float(f2tf32(v.y));
                As[r][c+2] = __uint_as_float(f2tf32(v.z));
                As[r][c+3] = __uint_as_float(f2tf32(v.w));
            }
        } else {
            int k = tid >> 3, mb = tid & 7;
            const float* ak = A + (size_t)(k0 + k) * lda + m0;
            #pragma unroll
            for (int i = 0; i < 16; i++) {
                int m = mb + i*8;
                As[m][k] = __uint_as_float(f2tf32(ak[m]));
            }
        }
        {
            int r = tid >> 2, c = (tid & 3) * 8;
            float4 v0 = *(const float4*)(B + (size_t)(n0+r)*K + k0 + c);
            float4 v1 = *(const float4*)(B + (size_t)(n0+r)*K + k0 + c + 4);
            Bs[r][c+0] = __uint_as_float(f2tf32(v0.x));
            Bs[r][c+1] = __uint_as_float(f2tf32(v0.y));
            Bs[r][c+2] = __uint_as_float(f2tf32(v0.z));
            Bs[r][c+3] = __uint_as_float(f2tf32(v0.w));
            Bs[r][c+4] = __uint_as_float(f2tf32(v1.x));
            Bs[r][c+5] = __uint_as_float(f2tf32(v1.y));
            Bs[r][c+6] = __uint_as_float(f2tf32(v1.z));
            Bs[r][c+7] = __uint_as_float(f2tf32(v1.w));
        }
        __syncthreads();

        #pragma unroll
        for (int kk = 0; kk < 32; kk += 8) {
            unsigned a[2][4], bfr[4][2];
            #pragma unroll
            for (int mi = 0; mi < 2; mi++) {
                int rb = wm0 + mi*16;
                a[mi][0] = __float_as_uint(As[rb+gid  ][kk+tig  ]);
                a[mi][1] = __float_as_uint(As[rb+gid+8][kk+tig  ]);
                a[mi][2] = __float_as_uint(As[rb+gid  ][kk+tig+4]);
                a[mi][3] = __float_as_uint(As[rb+gid+8][kk+tig+4]);
            }
            #pragma unroll
            for (int nf = 0; nf < 4; nf++) {
                bfr[nf][0] = __float_as_uint(Bs[wn0+nf*8+gid][kk+tig  ]);
                bfr[nf][1] = __float_as_uint(Bs[wn0+nf*8+gid][kk+tig+4]);
            }
            #pragma unroll
            for (int mi = 0; mi < 2; mi++)
                #pragma unroll
                for (int nf = 0; nf < 4; nf++)
                    mma_tf32(acc[mi][nf], a[mi][0], a[mi][1], a[mi][2], a[mi][3],
                             bfr[nf][0], bfr[nf][1]);
        }
        __syncthreads();
    }

    #pragma unroll
    for (int mi = 0; mi < 2; mi++) {
        int r0 = m0 + wm0 + mi*16 + gid;
        #pragma unroll
        for (int nf = 0; nf < 4; nf++) {
            int col = n0 + wn0 + nf*8 + 2*tig;
            float v0 = acc[mi][nf][0], v1 = acc[mi][nf][1];
            float v2 = acc[mi][nf][2], v3 = acc[mi][nf][3];
            if (bias) {
                if (biasPerM) {
                    float b0 = bias[r0], b1 = bias[r0+8];
                    v0 += b0; v1 += b0; v2 += b1; v3 += b1;
                } else {
                    float b0 = bias[col], b1 = bias[col+1];
                    v0 += b0; v1 += b1; v2 += b0; v3 += b1;
                }
            }
            if (doGelu) { v0 = gelu_f(v0); v1 = gelu_f(v1); v2 = gelu_f(v2); v3 = gelu_f(v3); }
            float* cl = C + (size_t)r0*ldc + col;
            float* ch = C + (size_t)(r0+8)*ldc + col;
            if (doResid) {
                float2 o0 = *(float2*)cl, o1 = *(float2*)ch;
                v0 += o0.x; v1 += o0.y; v2 += o1.x; v3 += o1.y;
            }
            *(float2*)cl = make_float2(v0, v1);
            *(float2*)ch = make_float2(v2, v3);
        }
    }
}

// ---------------- fused flash attention, tf32 mma, 128-query tiles ----------------
// Block = 128 threads (4 warps). Warp w owns query rows [n0 + w*32, +32) as 2 m-frags.
// Dynamic smem layout (floats):
//   [0,     2304)  Ks 64x36
//   [2304,  4608)  Vs 64x36
//   [4608, 13312)  P  4 warps x 32 rows x 68  (first 4608 reused for Q staging 128x36)
#define ATTN_SMEM_BYTES ((4608 + 4*32*68) * 4)
__global__ void __launch_bounds__(128) attn_k(
    const float* __restrict__ qkv, const float* __restrict__ biasf,
    float* __restrict__ o)
{
    extern __shared__ float sm[];
    float (*Ks)[36] = (float(*)[36])sm;
    float (*Vs)[36] = (float(*)[36])(sm + 2304);
    float* Pbase = sm + 4608;

    int bh = blockIdx.y; int b = bh >> 3, h = bh & 7;
    int n0 = blockIdx.x * 128;

    int tid = threadIdx.x;
    int warp = tid >> 5, lane = tid & 31;
    int gid = lane >> 2, tig = lane & 3;
    int wrow = warp * 32;

    const float* qbase = qkv + (size_t)b*TOKS*768 + h*32;
    const float* bias_h = biasf + ((size_t)h << 20);

    // ---- stage Q (128 rows x 32) into P region (stride 36), pre-scaled + tf32 ----
    {
        float (*Qs)[36] = (float(*)[36])Pbase;
        int c = (tid & 7) * 4, r0 = tid >> 3;
        #pragma unroll
        for (int p = 0; p < 8; p++) {
            int r = r0 + p*16;
            float4 v = *(const float4*)(qbase + (size_t)(n0 + r)*768 + c);
            Qs[r][c+0] = __uint_as_float(f2tf32(v.x * SCALE_ATTN));
            Qs[r][c+1] = __uint_as_float(f2tf32(v.y * SCALE_ATTN));
            Qs[r][c+2] = __uint_as_float(f2tf32(v.z * SCALE_ATTN));
            Qs[r][c+3] = __uint_as_float(f2tf32(v.w * SCALE_ATTN));
        }
    }
    __syncthreads();

    // ---- extract Q fragments; after the loop's first barrier the region becomes P ----
    unsigned qa[2][4][4];
    {
        float (*Qs)[36] = (float(*)[36])Pbase;
        #pragma unroll
        for (int mi = 0; mi < 2; mi++) {
            int rb = wrow + mi*16;
            #pragma unroll
            for (int kki = 0; kki < 4; kki++) {
                int kk = kki * 8;
                qa[mi][kki][0] = __float_as_uint(Qs[rb+gid  ][kk+tig  ]);
                qa[mi][kki][1] = __float_as_uint(Qs[rb+gid+8][kk+tig  ]);
                qa[mi][kki][2] = __float_as_uint(Qs[rb+gid  ][kk+tig+4]);
                qa[mi][kki][3] = __float_as_uint(Qs[rb+gid+8][kk+tig+4]);
            }
        }
    }
    float (*Psw)[68] = (float(*)[68])(Pbase + warp*32*68);

    float m_run[4] = {-1e30f, -1e30f, -1e30f, -1e30f};
    float l_run[4] = {0.f, 0.f, 0.f, 0.f};
    float Oacc[2][4][4] = {};

    for (int k0 = 0; k0 < TOKS; k0 += 64) {
        __syncthreads();   // Q extraction (iter 0) / prev PV done before restaging
        {
            int c = (tid & 7) * 4, r0 = tid >> 3;
            #pragma unroll
            for (int p = 0; p < 4; p++) {
                int r = r0 + p*16;
                float4 kv = *(const float4*)(qbase + 256 + (size_t)(k0 + r)*768 + c);
                float4 vv = *(const float4*)(qbase + 512 + (size_t)(k0 + r)*768 + c);
                Ks[r][c+0] = __uint_as_float(f2tf32(kv.x));
                Ks[r][c+1] = __uint_as_float(f2tf32(kv.y));
                Ks[r][c+2] = __uint_as_float(f2tf32(kv.z));
                Ks[r][c+3] = __uint_as_float(f2tf32(kv.w));
                Vs[r][c+0] = __uint_as_float(f2tf32(vv.x));
                Vs[r][c+1] = __uint_as_float(f2tf32(vv.y));
                Vs[r][c+2] = __uint_as_float(f2tf32(vv.z));
                Vs[r][c+3] = __uint_as_float(f2tf32(vv.w));
            }
        }
        __syncthreads();

        // ---- S = Q K^T ----
        float S[2][8][4] = {};
        #pragma unroll
        for (int kki = 0; kki < 4; kki++) {
            int kk = kki * 8;
            #pragma unroll
            for (int nf = 0; nf < 8; nf++) {
                unsigned b0 = __float_as_uint(Ks[nf*8+gid][kk+tig  ]);
                unsigned b1 = __float_as_uint(Ks[nf*8+gid][kk+tig+4]);
                mma_tf32(S[0][nf], qa[0][kki][0], qa[0][kki][1], qa[0][kki][2], qa[0][kki][3], b0, b1);
                mma_tf32(S[1][nf], qa[1][kki][0], qa[1][kki][1], qa[1][kki][2], qa[1][kki][3], b0, b1);
            }
        }

        // ---- add combined bias, row max ----
        float mloc[4] = {-1e30f, -1e30f, -1e30f, -1e30f};
        #pragma unroll
        for (int mi = 0; mi < 2; mi++) {
            int n_a = n0 + wrow + mi*16 + gid;
            const float* ba = bias_h + (size_t)n_a*1024 + k0;
            const float* bb = ba + 8*1024;
            #pragma unroll
            for (int nf = 0; nf < 8; nf++) {
                int m = nf*8 + 2*tig;
                float2 ga = *(const float2*)(ba + m);
                float2 gc = *(const float2*)(bb + m);
                S[mi][nf][0] += ga.x; S[mi][nf][1] += ga.y;
                S[mi][nf][2] += gc.x; S[mi][nf][3] += gc.y;
                mloc[2*mi  ] = fmaxf(mloc[2*mi  ], fmaxf(S[mi][nf][0], S[mi][nf][1]));
                mloc[2*mi+1] = fmaxf(mloc[2*mi+1], fmaxf(S[mi][nf][2], S[mi][nf][3]));
            }
        }
        #pragma unroll
        for (int off = 1; off < 4; off <<= 1) {
            #pragma unroll
            for (int j = 0; j < 4; j++)
                mloc[j] = fmaxf(mloc[j], __shfl_xor_sync(0xffffffffu, mloc[j], off));
        }

        // ---- online softmax ----
        float mn[4], al[4], sl[4] = {0.f, 0.f, 0.f, 0.f};
        #pragma unroll
        for (int j = 0; j < 4; j++) {
            mn[j] = fmaxf(m_run[j], mloc[j]);
            al[j] = __expf(m_run[j] - mn[j]);
        }
        #pragma unroll
        for (int mi = 0; mi < 2; mi++) {
            #pragma unroll
            for (int nf = 0; nf < 8; nf++) {
                S[mi][nf][0] = __expf(S[mi][nf][0] - mn[2*mi]);
                S[mi][nf][1] = __expf(S[mi][nf][1] - mn[2*mi]);
                S[mi][nf][2] = __expf(S[mi][nf][2] - mn[2*mi+1]);
                S[mi][nf][3] = __expf(S[mi][nf][3] - mn[2*mi+1]);
                sl[2*mi  ] += S[mi][nf][0] + S[mi][nf][1];
                sl[2*mi+1] += S[mi][nf][2] + S[mi][nf][3];
                Psw[mi*16+gid  ][nf*8 + 2*tig    ] = __uint_as_float(f2tf32(S[mi][nf][0]));
                Psw[mi*16+gid  ][nf*8 + 2*tig + 1] = __uint_as_float(f2tf32(S[mi][nf][1]));
                Psw[mi*16+gid+8][nf*8 + 2*tig    ] = __uint_as_float(f2tf32(S[mi][nf][2]));
                Psw[mi*16+gid+8][nf*8 + 2*tig + 1] = __uint_as_float(f2tf32(S[mi][nf][3]));
            }
        }
        #pragma unroll
        for (int off = 1; off < 4; off <<= 1) {
            #pragma unroll
            for (int j = 0; j < 4; j++)
                sl[j] += __shfl_xor_sync(0xffffffffu, sl[j], off);
        }
        #pragma unroll
        for (int j = 0; j < 4; j++) {
            l_run[j] = l_run[j]*al[j] + sl[j];
            m_run[j] = mn[j];
        }
        #pragma unroll
        for (int mi = 0; mi < 2; mi++)
            #pragma unroll
            for (int df = 0; df < 4; df++) {
                Oacc[mi][df][0] *= al[2*mi];   Oacc[mi][df][1] *= al[2*mi];
                Oacc[mi][df][2] *= al[2*mi+1]; Oacc[mi][df][3] *= al[2*mi+1];
            }
        __syncwarp();

        // ---- O += P @ V ----
        #pragma unroll
        for (int kk = 0; kk < 64; kk += 8) {
            unsigned vb0[4], vb1[4];
            #pragma unroll
            for (int df = 0; df < 4; df++) {
                vb0[df] = __float_as_uint(Vs[kk+tig  ][df*8+gid]);
                vb1[df] = __float_as_uint(Vs[kk+tig+4][df*8+gid]);
            }
            #pragma unroll
            for (int mi = 0; mi < 2; mi++) {
                unsigned a0 = __float_as_uint(Psw[mi*16+gid  ][kk+tig  ]);
                unsigned a1 = __float_as_uint(Psw[mi*16+gid+8][kk+tig  ]);
                unsigned a2 = __float_as_uint(Psw[mi*16+gid  ][kk+tig+4]);
                unsigned a3 = __float_as_uint(Psw[mi*16+gid+8][kk+tig+4]);
                #pragma unroll
                for (int df = 0; df < 4; df++)
                    mma_tf32(Oacc[mi][df], a0, a1, a2, a3, vb0[df], vb1[df]);
            }
        }
    }

    // ---- epilogue ----
    #pragma unroll
    for (int j = 0; j < 4; j++) {
        int mi = j >> 1, half = j & 1;
        float inv = 1.f / l_run[j];
        int row = n0 + wrow + mi*16 + gid + half*8;
        float* op = o + (size_t)(b*TOKS + row)*EMB + h*32;
        #pragma unroll
        for (int df = 0; df < 4; df++) {
            *(float2*)(op + df*8 + 2*tig) =
                make_float2(Oacc[mi][df][half*2]*inv, Oacc[mi][df][half*2+1]*inv);
        }
    }
}

// ---------------- depthwise 3x3 dilation-2 conv + bias + gelu ----------------
__global__ void __launch_bounds__(256) dwconv_k(
    const float* __restrict__ hid, const float* __restrict__ wd,
    const float* __restrict__ bd, float* __restrict__ out)
{
    int bc = blockIdx.x;
    int c = bc & 511;
    __shared__ float t[32][32];
    const float* in = hid + (size_t)bc*1024;
    int tid = threadIdx.x;
    #pragma unroll
    for (int i = 0; i < 4; i++) { int p = tid + i*256; t[p>>5][p&31] = in[p]; }
    __syncthreads();
    float w[9];
    #pragma unroll
    for (int i = 0; i < 9; i++) w[i] = wd[c*9 + i];
    float bias = bd[c];
    #pragma unroll
    for (int i = 0; i < 4; i++) {
        int p = tid + i*256; int r = p >> 5, col = p & 31;
        float s = bias;
        #pragma unroll
        for (int u = 0; u < 3; u++)
            #pragma unroll
            for (int v = 0; v < 3; v++) {
                int rr = r + (u-1)*2, cc = col + (v-1)*2;
                if (rr >= 0 && rr < 32 && cc >= 0 && cc < 32)
                    s = fmaf(t[rr][cc], w[u*3+v], s);
            }
        out[(size_t)bc*1024 + p] = gelu_f(s);
    }
}

// ---------------- orchestration ----------------
extern "C" void kernel_launch(void* const* d_in, const int* in_sizes, int n_in,
                              void* d_out, int out_size)
{
    const float* x     = (const float*)d_in[0];
    const float* pw    = (const float*)d_in[1];
    const float* pb    = (const float*)d_in[2];
    const float* te    = (const float*)d_in[3];
    const float* qkvw  = (const float*)d_in[4];
    const float* projw = (const float*)d_in[5];
    const float* projb = (const float*)d_in[6];
    const float* ln1g  = (const float*)d_in[7];
    const float* ln1b  = (const float*)d_in[8];
    const float* ln2g  = (const float*)d_in[9];
    const float* ln2b  = (const float*)d_in[10];
    const float* rpbt  = (const float*)d_in[11];
    const float* gb    = (const float*)d_in[12];
    const float* pw1w  = (const float*)d_in[13];
    const float* pw1b  = (const float*)d_in[14];
    const float* dww   = (const float*)d_in[15];
    const float* dwb   = (const float*)d_in[16];
    const float* pw2w  = (const float*)d_in[17];
    const float* pw2b  = (const float*)d_in[18];
    float* tok = (float*)d_out;

    float *yb, *qkvb, *ob, *big;
    cudaGetSymbolAddress((void**)&yb,   g_y);
    cudaGetSymbolAddress((void**)&qkvb, g_qkv);
    cudaGetSymbolAddress((void**)&ob,   g_o);
    cudaGetSymbolAddress((void**)&big,  g_big);
    float* biasf = big;                              // attention phase
    float* hid   = big;                              // MLP phase (first half)
    float* hid2  = big + (size_t)BBATCH*HIDDEN*TOKS; // MLP phase (second half)

    cudaFuncSetAttribute(attn_k, cudaFuncAttributeMaxDynamicSharedMemorySize,
                         ATTN_SMEM_BYTES);

    patch_embed_k<<<BBATCH*TOKS, 256>>>(x, pw, pb, te, tok);

    for (int l = 0; l < NLAYER; l++) {
        // --- attention phase (g_big = biasf) ---
        biasprep_k<<<dim3(1024, 8), 256>>>(
            rpbt + (size_t)l*3969*NHEADS, gb + (size_t)l*1024*1024, biasf);
        layernorm_k<<<1024, 256>>>(tok, ln1g + l*EMB, ln1b + l*EMB, yb);
        // qkv = y @ qkv_w^T : M=8192, N=768, K=256
        gemm_tc<<<dim3(12, 64, 1), 256>>>(
            yb, 0, 0, EMB,
            qkvw + (size_t)l*768*EMB, 0,
            qkvb, 0, 768, nullptr, 0, 0, 0, EMB);
        attn_k<<<dim3(8, 64), 128, ATTN_SMEM_BYTES>>>(qkvb, biasf, ob);
        // tok += o @ proj_w^T + proj_b : M=8192, N=256, K=256
        gemm_tc<<<dim3(4, 64, 1), 256>>>(
            ob, 0, 0, EMB,
            projw + (size_t)l*EMB*EMB, 0,
            tok, 0, EMB, projb + l*EMB, 0, 0, 1, EMB);

        // --- MLP phase (g_big = hid | hid2; biasf is dead now) ---
        layernorm_k<<<1024, 256>>>(tok, ln2g + l*EMB, ln2b + l*EMB, yb);
        // hid[b][c][n] = gelu(W1·Y^T + b1[c]) : per-batch M=512, N=1024, K=256
        gemm_tc<<<dim3(16, 4, BBATCH), 256>>>(
            pw1w + (size_t)l*HIDDEN*EMB, 0, 0, EMB,
            yb, (size_t)TOKS*EMB,
            hid, (size_t)HIDDEN*TOKS, TOKS, pw1b + l*HIDDEN, 1, 1, 0, EMB);
        dwconv_k<<<BBATCH*HIDDEN, 256>>>(hid, dww + (size_t)l*HIDDEN*9, dwb + l*HIDDEN, hid2);
        // tok += hid2^T · W2^T + b2 : per-batch M=1024, N=256, K=512 (A transposed)
        gemm_tc<<<dim3(4, 8, BBATCH), 256>>>(
            hid2, (size_t)HIDDEN*TOKS, 1, TOKS,
            pw2w + (size_t)l*EMB*HIDDEN, 0,
            tok, (size_t)TOKS*EMB, EMB, pw2b + l*EMB, 0, 0, 1, HIDDEN);
    }
}

// round 8
// speedup vs baseline: 2.4189x; 1.0807x over previous
#include <cuda_runtime.h>
#include <math.h>

// ---------------- problem constants ----------------
#define TOKS   1024
#define EMB    256
#define NHEADS 8
#define HDIM   32
#define BBATCH 8
#define NLAYER 8
#define HIDDEN 512
#define SCALE_ATTN 0.17677669529663687f   // 32^-0.5

// ---------------- scratch (device globals; no allocation allowed) ----------------
// Total 72 MB — identical footprint to the last passing rounds.
__device__ float g_y   [BBATCH*TOKS*EMB];            // 8 MB
__device__ float g_qkv [BBATCH*TOKS*3*EMB];          // 24 MB
__device__ float g_o   [BBATCH*TOKS*EMB];            // 8 MB
// g_big is phase-overlaid:
//   attention phase: biasf[h][n][m] = rpb + gbias   (all 8M floats)
//   MLP phase:       hid  = g_big[0 .. 4M), hid2 = g_big[4M .. 8M)
__device__ float g_big [NHEADS*TOKS*TOKS];           // 32 MB

__device__ __forceinline__ float gelu_f(float x) {
    return 0.5f * x * (1.0f + erff(x * 0.70710678118654752f));
}

__device__ __forceinline__ unsigned f2tf32(float x) {
    unsigned u; asm("cvt.rna.tf32.f32 %0, %1;" : "=r"(u) : "f"(x)); return u;
}

__device__ __forceinline__ void mma_tf32(float* c,
    unsigned a0, unsigned a1, unsigned a2, unsigned a3,
    unsigned b0, unsigned b1)
{
    asm volatile(
        "mma.sync.aligned.m16n8k8.row.col.f32.tf32.tf32.f32 "
        "{%0,%1,%2,%3},{%4,%5,%6,%7},{%8,%9},{%0,%1,%2,%3};"
        : "+f"(c[0]), "+f"(c[1]), "+f"(c[2]), "+f"(c[3])
        : "r"(a0), "r"(a1), "r"(a2), "r"(a3), "r"(b0), "r"(b1));
}

// ---------------- patch embed ----------------
__global__ void __launch_bounds__(256) patch_embed_k(
    const float* __restrict__ x, const float* __restrict__ pw,
    const float* __restrict__ pb, const float* __restrict__ te,
    float* __restrict__ tok)
{
    int t = blockIdx.x;
    int b = t >> 10, n = t & 1023;
    int pi = n >> 5, pj = n & 31;
    __shared__ float patch[64];
    int tid = threadIdx.x;
    if (tid < 64) {
        int r = tid >> 3, c = tid & 7;
        patch[tid] = x[((size_t)b*256 + (size_t)pi*8 + r)*256 + pj*8 + c];
    }
    __syncthreads();
    float acc = pb[tid] + te[tid];
    const float* w = pw + tid*64;
    #pragma unroll
    for (int k = 0; k < 64; k++) acc = fmaf(w[k], patch[k], acc);
    tok[(size_t)t*EMB + tid] = acc;
}

// ---------------- layernorm ----------------
__global__ void __launch_bounds__(256) layernorm_k(
    const float* __restrict__ in, const float* __restrict__ g,
    const float* __restrict__ bta, float* __restrict__ out)
{
    int warp = threadIdx.x >> 5, lane = threadIdx.x & 31;
    size_t t = (size_t)blockIdx.x*8 + warp;
    const float* row = in + t*EMB;
    float v[8]; float s = 0.f;
    #pragma unroll
    for (int i = 0; i < 8; i++) { v[i] = row[lane + i*32]; s += v[i]; }
    #pragma unroll
    for (int o = 16; o; o >>= 1) s += __shfl_xor_sync(0xffffffffu, s, o);
    float mean = s * (1.f/256.f);
    float var = 0.f;
    #pragma unroll
    for (int i = 0; i < 8; i++) { float d = v[i]-mean; var += d*d; }
    #pragma unroll
    for (int o = 16; o; o >>= 1) var += __shfl_xor_sync(0xffffffffu, var, o);
    float r = rsqrtf(var * (1.f/256.f) + 1e-5f);
    float* orow = out + t*EMB;
    #pragma unroll
    for (int i = 0; i < 8; i++) {
        int c = lane + i*32;
        orow[c] = (v[i]-mean)*r*g[c] + bta[c];
    }
}

// ---------------- combined attention bias: out[h][n][m] = rpb + gbias ----------------
__global__ void __launch_bounds__(256) biasprep_k(
    const float* __restrict__ rt, const float* __restrict__ gb,
    float* __restrict__ out)
{
    int n = blockIdx.x, h = blockIdx.y;
    int m0 = threadIdx.x * 4;
    int i1 = n >> 5, j1 = n & 31;
    float4 g = *(const float4*)(gb + (size_t)n*1024 + m0);
    float4 v;
    {
        int m = m0;
        v.x = rt[((i1-(m>>5)+31)*63 + (j1-(m&31)+31))*NHEADS + h] + g.x;
        m = m0+1;
        v.y = rt[((i1-(m>>5)+31)*63 + (j1-(m&31)+31))*NHEADS + h] + g.y;
        m = m0+2;
        v.z = rt[((i1-(m>>5)+31)*63 + (j1-(m&31)+31))*NHEADS + h] + g.z;
        m = m0+3;
        v.w = rt[((i1-(m>>5)+31)*63 + (j1-(m&31)+31))*NHEADS + h] + g.w;
    }
    *(float4*)(out + (((size_t)h<<20) | ((size_t)n<<10)) + m0) = v;
}

// ---------------- tf32 tensor-core GEMM, register-double-buffered pipeline ----------------
// C[M,N] (+)= A · B^T.  A: [M,K] k-contig (TRANSA=0) or A[m + k*lda] (TRANSA=1).
// B: [N,K] k-contig.  Tile 128x64x32, 256 threads, 8 warps (4x2).
template<int TRANSA>
__global__ void __launch_bounds__(256) gemm_tc(
    const float* __restrict__ A, size_t sAb, int lda,
    const float* __restrict__ B, size_t sBb,
    float* __restrict__ C, size_t sCb, int ldc,
    const float* __restrict__ bias, int biasPerM, int doGelu, int doResid,
    int K)
{
    __shared__ float As[128][36];
    __shared__ float Bs[64][36];
    A += (size_t)blockIdx.z * sAb;
    B += (size_t)blockIdx.z * sBb;
    C += (size_t)blockIdx.z * sCb;
    int m0 = blockIdx.y * 128, n0 = blockIdx.x * 64;
    int tid = threadIdx.x;
    int warp = tid >> 5, lane = tid & 31;
    int gid = lane >> 2, tig = lane & 3;
    int wm0 = (warp & 3) * 32, wn0 = (warp >> 2) * 32;

    float acc[2][4][4] = {};
    float ar[16], br[8];

    // thread->tile mappings for staging
    int a_r0 = tid >> 3, a_c = (tid & 7) * 4;     // TRANSA=0: 4 rows x 4 cols
    int a_k  = tid >> 3, a_mb = tid & 7;          // TRANSA=1: 1 col  x 16 rows
    int b_r  = tid >> 2, b_c = (tid & 3) * 8;     // 1 row x 8 cols

    // ---- register loads for K-chunk k0 ----
    auto loadA = [&](int k0) {
        if (!TRANSA) {
            #pragma unroll
            for (int i = 0; i < 4; i++) {
                float4 v = *(const float4*)(A + (size_t)(m0 + a_r0 + i*32)*lda + k0 + a_c);
                ar[i*4+0]=v.x; ar[i*4+1]=v.y; ar[i*4+2]=v.z; ar[i*4+3]=v.w;
            }
        } else {
            const float* ak = A + (size_t)(k0 + a_k)*lda + m0;
            #pragma unroll
            for (int i = 0; i < 16; i++) ar[i] = ak[a_mb + i*8];
        }
    };
    auto loadB = [&](int k0) {
        float4 v0 = *(const float4*)(B + (size_t)(n0 + b_r)*K + k0 + b_c);
        float4 v1 = *(const float4*)(B + (size_t)(n0 + b_r)*K + k0 + b_c + 4);
        br[0]=v0.x; br[1]=v0.y; br[2]=v0.z; br[3]=v0.w;
        br[4]=v1.x; br[5]=v1.y; br[6]=v1.z; br[7]=v1.w;
    };
    auto storeAB = [&]() {
        if (!TRANSA) {
            #pragma unroll
            for (int i = 0; i < 4; i++) {
                int r = a_r0 + i*32;
                As[r][a_c+0] = __uint_as_float(f2tf32(ar[i*4+0]));
                As[r][a_c+1] = __uint_as_float(f2tf32(ar[i*4+1]));
                As[r][a_c+2] = __uint_as_float(f2tf32(ar[i*4+2]));
                As[r][a_c+3] = __uint_as_float(f2tf32(ar[i*4+3]));
            }
        } else {
            #pragma unroll
            for (int i = 0; i < 16; i++)
                As[a_mb + i*8][a_k] = __uint_as_float(f2tf32(ar[i]));
        }
        #pragma unroll
        for (int i = 0; i < 8; i++)
            Bs[b_r][b_c+i] = __uint_as_float(f2tf32(br[i]));
    };

    int niter = K >> 5;
    loadA(0); loadB(0);

    for (int i = 0; i < niter; i++) {
        storeAB();
        __syncthreads();
        if (i + 1 < niter) { loadA((i+1) << 5); loadB((i+1) << 5); }

        #pragma unroll
        for (int kk = 0; kk < 32; kk += 8) {
            unsigned a[2][4], bfr[4][2];
            #pragma unroll
            for (int mi = 0; mi < 2; mi++) {
                int rb = wm0 + mi*16;
                a[mi][0] = __float_as_uint(As[rb+gid  ][kk+tig  ]);
                a[mi][1] = __float_as_uint(As[rb+gid+8][kk+tig  ]);
                a[mi][2] = __float_as_uint(As[rb+gid  ][kk+tig+4]);
                a[mi][3] = __float_as_uint(As[rb+gid+8][kk+tig+4]);
            }
            #pragma unroll
            for (int nf = 0; nf < 4; nf++) {
                bfr[nf][0] = __float_as_uint(Bs[wn0+nf*8+gid][kk+tig  ]);
                bfr[nf][1] = __float_as_uint(Bs[wn0+nf*8+gid][kk+tig+4]);
            }
            #pragma unroll
            for (int mi = 0; mi < 2; mi++)
                #pragma unroll
                for (int nf = 0; nf < 4; nf++)
                    mma_tf32(acc[mi][nf], a[mi][0], a[mi][1], a[mi][2], a[mi][3],
                             bfr[nf][0], bfr[nf][1]);
        }
        __syncthreads();
    }

    #pragma unroll
    for (int mi = 0; mi < 2; mi++) {
        int r0 = m0 + wm0 + mi*16 + gid;
        #pragma unroll
        for (int nf = 0; nf < 4; nf++) {
            int col = n0 + wn0 + nf*8 + 2*tig;
            float v0 = acc[mi][nf][0], v1 = acc[mi][nf][1];
            float v2 = acc[mi][nf][2], v3 = acc[mi][nf][3];
            if (bias) {
                if (biasPerM) {
                    float b0 = bias[r0], b1 = bias[r0+8];
                    v0 += b0; v1 += b0; v2 += b1; v3 += b1;
                } else {
                    float b0 = bias[col], b1 = bias[col+1];
                    v0 += b0; v1 += b1; v2 += b0; v3 += b1;
                }
            }
            if (doGelu) { v0 = gelu_f(v0); v1 = gelu_f(v1); v2 = gelu_f(v2); v3 = gelu_f(v3); }
            float* cl = C + (size_t)r0*ldc + col;
            float* ch = C + (size_t)(r0+8)*ldc + col;
            if (doResid) {
                float2 o0 = *(float2*)cl, o1 = *(float2*)ch;
                v0 += o0.x; v1 += o0.y; v2 += o1.x; v3 += o1.y;
            }
            *(float2*)cl = make_float2(v0, v1);
            *(float2*)ch = make_float2(v2, v3);
        }
    }
}

// ---------------- fused flash attention, tf32 mma, 128-query tiles ----------------
// Block = 128 threads (4 warps). Warp w owns query rows [n0 + w*32, +32) as 2 m-frags.
// Dynamic smem layout (floats):
//   [0,     2304)  Ks 64x36
//   [2304,  4608)  Vs 64x36
//   [4608, 13312)  P  4 warps x 32 rows x 68  (first 4608 reused for Q staging 128x36)
#define ATTN_SMEM_BYTES ((4608 + 4*32*68) * 4)
__global__ void __launch_bounds__(128) attn_k(
    const float* __restrict__ qkv, const float* __restrict__ biasf,
    float* __restrict__ o)
{
    extern __shared__ float sm[];
    float (*Ks)[36] = (float(*)[36])sm;
    float (*Vs)[36] = (float(*)[36])(sm + 2304);
    float* Pbase = sm + 4608;

    int bh = blockIdx.y; int b = bh >> 3, h = bh & 7;
    int n0 = blockIdx.x * 128;

    int tid = threadIdx.x;
    int warp = tid >> 5, lane = tid & 31;
    int gid = lane >> 2, tig = lane & 3;
    int wrow = warp * 32;

    const float* qbase = qkv + (size_t)b*TOKS*768 + h*32;
    const float* bias_h = biasf + ((size_t)h << 20);

    // ---- stage Q (128 rows x 32) into P region (stride 36), pre-scaled + tf32 ----
    {
        float (*Qs)[36] = (float(*)[36])Pbase;
        int c = (tid & 7) * 4, r0 = tid >> 3;
        #pragma unroll
        for (int p = 0; p < 8; p++) {
            int r = r0 + p*16;
            float4 v = *(const float4*)(qbase + (size_t)(n0 + r)*768 + c);
            Qs[r][c+0] = __uint_as_float(f2tf32(v.x * SCALE_ATTN));
            Qs[r][c+1] = __uint_as_float(f2tf32(v.y * SCALE_ATTN));
            Qs[r][c+2] = __uint_as_float(f2tf32(v.z * SCALE_ATTN));
            Qs[r][c+3] = __uint_as_float(f2tf32(v.w * SCALE_ATTN));
        }
    }
    __syncthreads();

    // ---- extract Q fragments; after the loop's first barrier the region becomes P ----
    unsigned qa[2][4][4];
    {
        float (*Qs)[36] = (float(*)[36])Pbase;
        #pragma unroll
        for (int mi = 0; mi < 2; mi++) {
            int rb = wrow + mi*16;
            #pragma unroll
            for (int kki = 0; kki < 4; kki++) {
                int kk = kki * 8;
                qa[mi][kki][0] = __float_as_uint(Qs[rb+gid  ][kk+tig  ]);
                qa[mi][kki][1] = __float_as_uint(Qs[rb+gid+8][kk+tig  ]);
                qa[mi][kki][2] = __float_as_uint(Qs[rb+gid  ][kk+tig+4]);
                qa[mi][kki][3] = __float_as_uint(Qs[rb+gid+8][kk+tig+4]);
            }
        }
    }
    float (*Psw)[68] = (float(*)[68])(Pbase + warp*32*68);

    float m_run[4] = {-1e30f, -1e30f, -1e30f, -1e30f};
    float l_run[4] = {0.f, 0.f, 0.f, 0.f};
    float Oacc[2][4][4] = {};

    for (int k0 = 0; k0 < TOKS; k0 += 64) {
        __syncthreads();   // Q extraction (iter 0) / prev PV done before restaging
        {
            int c = (tid & 7) * 4, r0 = tid >> 3;
            #pragma unroll
            for (int p = 0; p < 4; p++) {
                int r = r0 + p*16;
                float4 kv = *(const float4*)(qbase + 256 + (size_t)(k0 + r)*768 + c);
                float4 vv = *(const float4*)(qbase + 512 + (size_t)(k0 + r)*768 + c);
                Ks[r][c+0] = __uint_as_float(f2tf32(kv.x));
                Ks[r][c+1] = __uint_as_float(f2tf32(kv.y));
                Ks[r][c+2] = __uint_as_float(f2tf32(kv.z));
                Ks[r][c+3] = __uint_as_float(f2tf32(kv.w));
                Vs[r][c+0] = __uint_as_float(f2tf32(vv.x));
                Vs[r][c+1] = __uint_as_float(f2tf32(vv.y));
                Vs[r][c+2] = __uint_as_float(f2tf32(vv.z));
                Vs[r][c+3] = __uint_as_float(f2tf32(vv.w));
            }
        }
        __syncthreads();

        // ---- S = Q K^T ----
        float S[2][8][4] = {};
        #pragma unroll
        for (int kki = 0; kki < 4; kki++) {
            int kk = kki * 8;
            #pragma unroll
            for (int nf = 0; nf < 8; nf++) {
                unsigned b0 = __float_as_uint(Ks[nf*8+gid][kk+tig  ]);
                unsigned b1 = __float_as_uint(Ks[nf*8+gid][kk+tig+4]);
                mma_tf32(S[0][nf], qa[0][kki][0], qa[0][kki][1], qa[0][kki][2], qa[0][kki][3], b0, b1);
                mma_tf32(S[1][nf], qa[1][kki][0], qa[1][kki][1], qa[1][kki][2], qa[1][kki][3], b0, b1);
            }
        }

        // ---- add combined bias, row max ----
        float mloc[4] = {-1e30f, -1e30f, -1e30f, -1e30f};
        #pragma unroll
        for (int mi = 0; mi < 2; mi++) {
            int n_a = n0 + wrow + mi*16 + gid;
            const float* ba = bias_h + (size_t)n_a*1024 + k0;
            const float* bb = ba + 8*1024;
            #pragma unroll
            for (int nf = 0; nf < 8; nf++) {
                int m = nf*8 + 2*tig;
                float2 ga = *(const float2*)(ba + m);
                float2 gc = *(const float2*)(bb + m);
                S[mi][nf][0] += ga.x; S[mi][nf][1] += ga.y;
                S[mi][nf][2] += gc.x; S[mi][nf][3] += gc.y;
                mloc[2*mi  ] = fmaxf(mloc[2*mi  ], fmaxf(S[mi][nf][0], S[mi][nf][1]));
                mloc[2*mi+1] = fmaxf(mloc[2*mi+1], fmaxf(S[mi][nf][2], S[mi][nf][3]));
            }
        }
        #pragma unroll
        for (int off = 1; off < 4; off <<= 1) {
            #pragma unroll
            for (int j = 0; j < 4; j++)
                mloc[j] = fmaxf(mloc[j], __shfl_xor_sync(0xffffffffu, mloc[j], off));
        }

        // ---- online softmax ----
        float mn[4], al[4], sl[4] = {0.f, 0.f, 0.f, 0.f};
        #pragma unroll
        for (int j = 0; j < 4; j++) {
            mn[j] = fmaxf(m_run[j], mloc[j]);
            al[j] = __expf(m_run[j] - mn[j]);
        }
        #pragma unroll
        for (int mi = 0; mi < 2; mi++) {
            #pragma unroll
            for (int nf = 0; nf < 8; nf++) {
                S[mi][nf][0] = __expf(S[mi][nf][0] - mn[2*mi]);
                S[mi][nf][1] = __expf(S[mi][nf][1] - mn[2*mi]);
                S[mi][nf][2] = __expf(S[mi][nf][2] - mn[2*mi+1]);
                S[mi][nf][3] = __expf(S[mi][nf][3] - mn[2*mi+1]);
                sl[2*mi  ] += S[mi][nf][0] + S[mi][nf][1];
                sl[2*mi+1] += S[mi][nf][2] + S[mi][nf][3];
                Psw[mi*16+gid  ][nf*8 + 2*tig    ] = __uint_as_float(f2tf32(S[mi][nf][0]));
                Psw[mi*16+gid  ][nf*8 + 2*tig + 1] = __uint_as_float(f2tf32(S[mi][nf][1]));
                Psw[mi*16+gid+8][nf*8 + 2*tig    ] = __uint_as_float(f2tf32(S[mi][nf][2]));
                Psw[mi*16+gid+8][nf*8 + 2*tig + 1] = __uint_as_float(f2tf32(S[mi][nf][3]));
            }
        }
        #pragma unroll
        for (int off = 1; off < 4; off <<= 1) {
            #pragma unroll
            for (int j = 0; j < 4; j++)
                sl[j] += __shfl_xor_sync(0xffffffffu, sl[j], off);
        }
        #pragma unroll
        for (int j = 0; j < 4; j++) {
            l_run[j] = l_run[j]*al[j] + sl[j];
            m_run[j] = mn[j];
        }
        #pragma unroll
        for (int mi = 0; mi < 2; mi++)
            #pragma unroll
            for (int df = 0; df < 4; df++) {
                Oacc[mi][df][0] *= al[2*mi];   Oacc[mi][df][1] *= al[2*mi];
                Oacc[mi][df][2] *= al[2*mi+1]; Oacc[mi][df][3] *= al[2*mi+1];
            }
        __syncwarp();

        // ---- O += P @ V ----
        #pragma unroll
        for (int kk = 0; kk < 64; kk += 8) {
            unsigned vb0[4], vb1[4];
            #pragma unroll
            for (int df = 0; df < 4; df++) {
                vb0[df] = __float_as_uint(Vs[kk+tig  ][df*8+gid]);
                vb1[df] = __float_as_uint(Vs[kk+tig+4][df*8+gid]);
            }
            #pragma unroll
            for (int mi = 0; mi < 2; mi++) {
                unsigned a0 = __float_as_uint(Psw[mi*16+gid  ][kk+tig  ]);
                unsigned a1 = __float_as_uint(Psw[mi*16+gid+8][kk+tig  ]);
                unsigned a2 = __float_as_uint(Psw[mi*16+gid  ][kk+tig+4]);
                unsigned a3 = __float_as_uint(Psw[mi*16+gid+8][kk+tig+4]);
                #pragma unroll
                for (int df = 0; df < 4; df++)
                    mma_tf32(Oacc[mi][df], a0, a1, a2, a3, vb0[df], vb1[df]);
            }
        }
    }

    // ---- epilogue ----
    #pragma unroll
    for (int j = 0; j < 4; j++) {
        int mi = j >> 1, half = j & 1;
        float inv = 1.f / l_run[j];
        int row = n0 + wrow + mi*16 + gid + half*8;
        float* op = o + (size_t)(b*TOKS + row)*EMB + h*32;
        #pragma unroll
        for (int df = 0; df < 4; df++) {
            *(float2*)(op + df*8 + 2*tig) =
                make_float2(Oacc[mi][df][half*2]*inv, Oacc[mi][df][half*2+1]*inv);
        }
    }
}

// ---------------- depthwise 3x3 dilation-2 conv + bias + gelu ----------------
__global__ void __launch_bounds__(256) dwconv_k(
    const float* __restrict__ hid, const float* __restrict__ wd,
    const float* __restrict__ bd, float* __restrict__ out)
{
    int bc = blockIdx.x;
    int c = bc & 511;
    __shared__ float t[32][32];
    const float* in = hid + (size_t)bc*1024;
    int tid = threadIdx.x;
    #pragma unroll
    for (int i = 0; i < 4; i++) { int p = tid + i*256; t[p>>5][p&31] = in[p]; }
    __syncthreads();
    float w[9];
    #pragma unroll
    for (int i = 0; i < 9; i++) w[i] = wd[c*9 + i];
    float bias = bd[c];
    #pragma unroll
    for (int i = 0; i < 4; i++) {
        int p = tid + i*256; int r = p >> 5, col = p & 31;
        float s = bias;
        #pragma unroll
        for (int u = 0; u < 3; u++)
            #pragma unroll
            for (int v = 0; v < 3; v++) {
                int rr = r + (u-1)*2, cc = col + (v-1)*2;
                if (rr >= 0 && rr < 32 && cc >= 0 && cc < 32)
                    s = fmaf(t[rr][cc], w[u*3+v], s);
            }
        out[(size_t)bc*1024 + p] = gelu_f(s);
    }
}

// ---------------- orchestration ----------------
extern "C" void kernel_launch(void* const* d_in, const int* in_sizes, int n_in,
                              void* d_out, int out_size)
{
    const float* x     = (const float*)d_in[0];
    const float* pw    = (const float*)d_in[1];
    const float* pb    = (const float*)d_in[2];
    const float* te    = (const float*)d_in[3];
    const float* qkvw  = (const float*)d_in[4];
    const float* projw = (const float*)d_in[5];
    const float* projb = (const float*)d_in[6];
    const float* ln1g  = (const float*)d_in[7];
    const float* ln1b  = (const float*)d_in[8];
    const float* ln2g  = (const float*)d_in[9];
    const float* ln2b  = (const float*)d_in[10];
    const float* rpbt  = (const float*)d_in[11];
    const float* gb    = (const float*)d_in[12];
    const float* pw1w  = (const float*)d_in[13];
    const float* pw1b  = (const float*)d_in[14];
    const float* dww   = (const float*)d_in[15];
    const float* dwb   = (const float*)d_in[16];
    const float* pw2w  = (const float*)d_in[17];
    const float* pw2b  = (const float*)d_in[18];
    float* tok = (float*)d_out;

    float *yb, *qkvb, *ob, *big;
    cudaGetSymbolAddress((void**)&yb,   g_y);
    cudaGetSymbolAddress((void**)&qkvb, g_qkv);
    cudaGetSymbolAddress((void**)&ob,   g_o);
    cudaGetSymbolAddress((void**)&big,  g_big);
    float* biasf = big;                              // attention phase
    float* hid   = big;                              // MLP phase (first half)
    float* hid2  = big + (size_t)BBATCH*HIDDEN*TOKS; // MLP phase (second half)

    cudaFuncSetAttribute(attn_k, cudaFuncAttributeMaxDynamicSharedMemorySize,
                         ATTN_SMEM_BYTES);

    patch_embed_k<<<BBATCH*TOKS, 256>>>(x, pw, pb, te, tok);

    for (int l = 0; l < NLAYER; l++) {
        // --- attention phase (g_big = biasf) ---
        biasprep_k<<<dim3(1024, 8), 256>>>(
            rpbt + (size_t)l*3969*NHEADS, gb + (size_t)l*1024*1024, biasf);
        layernorm_k<<<1024, 256>>>(tok, ln1g + l*EMB, ln1b + l*EMB, yb);
        // qkv = y @ qkv_w^T : M=8192, N=768, K=256
        gemm_tc<0><<<dim3(12, 64, 1), 256>>>(
            yb, 0, EMB,
            qkvw + (size_t)l*768*EMB, 0,
            qkvb, 0, 768, nullptr, 0, 0, 0, EMB);
        attn_k<<<dim3(8, 64), 128, ATTN_SMEM_BYTES>>>(qkvb, biasf, ob);
        // tok += o @ proj_w^T + proj_b : M=8192, N=256, K=256
        gemm_tc<0><<<dim3(4, 64, 1), 256>>>(
            ob, 0, EMB,
            projw + (size_t)l*EMB*EMB, 0,
            tok, 0, EMB, projb + l*EMB, 0, 0, 1, EMB);

        // --- MLP phase (g_big = hid | hid2; biasf is dead now) ---
        layernorm_k<<<1024, 256>>>(tok, ln2g + l*EMB, ln2b + l*EMB, yb);
        // hid[b][c][n] = gelu(W1·Y^T + b1[c]) : per-batch M=512, N=1024, K=256
        gemm_tc<0><<<dim3(16, 4, BBATCH), 256>>>(
            pw1w + (size_t)l*HIDDEN*EMB, 0, EMB,
            yb, (size_t)TOKS*EMB,
            hid, (size_t)HIDDEN*TOKS, TOKS, pw1b + l*HIDDEN, 1, 1, 0, EMB);
        dwconv_k<<<BBATCH*HIDDEN, 256>>>(hid, dww + (size_t)l*HIDDEN*9, dwb + l*HIDDEN, hid2);
        // tok += hid2^T · W2^T + b2 : per-batch M=1024, N=256, K=512 (A transposed)
        gemm_tc<1><<<dim3(4, 8, BBATCH), 256>>>(
            hid2, (size_t)HIDDEN*TOKS, TOKS,
            pw2w + (size_t)l*EMB*HIDDEN, 0,
            tok, (size_t)TOKS*EMB, EMB, pw2b + l*EMB, 0, 0, 1, HIDDEN);
    }
}